// round 4
// baseline (speedup 1.0000x reference)
#include <cuda_runtime.h>
#include <cuda_bf16.h>
#include <math_constants.h>

// Problem constants
#define BB   2
#define LL   2048
#define CC   512
#define HH   8
#define DD   64
#define MM   (BB*LL)          // 4096 rows
#define NQKV (3*CC)           // 1536
#define NQ   16               // L/128
#define NK   32               // L/64
#define SCALE 0.125f          // D^-0.5
#define SIMTH 0.6f
#define CDFTH 0.98f

// Scratch (allocation-free rule -> device globals)
__device__ float g_q[BB*HH*LL*DD];     // [B,H,L,D]
__device__ float g_k[BB*HH*LL*DD];
__device__ float g_v[BB*HH*LL*DD];
__device__ float g_o[BB*LL*CC];        // [B,L,C]
__device__ int   g_mask[BB*HH*NQ*NK];  // 1 = keep block

// ---------------------------------------------------------------------------
// Kernel 1: QKV GEMM  (x[4096,512] @ Wqkv[512,1536] + bqkv) scattered to q/k/v
// 64x64 tile, K-chunk 32, 256 threads, 4x4 microtile
// ---------------------------------------------------------------------------
__global__ void __launch_bounds__(256) sgemm_qkv(const float* __restrict__ A,
                                                 const float* __restrict__ Bw,
                                                 const float* __restrict__ bias) {
    const int K = CC, N = NQKV;
    int m0 = blockIdx.y * 64, n0 = blockIdx.x * 64;
    __shared__ float AsT[32][68];   // transposed, stride 68 keeps float4 16B-aligned
    __shared__ float Bs[32][64];
    int tid = threadIdx.x;
    int tx = tid & 15, ty = tid >> 4;
    float c[4][4] = {};

    for (int k0 = 0; k0 < K; k0 += 32) {
        #pragma unroll
        for (int i = 0; i < 2; i++) {
            int f4 = tid + i * 256;            // 512 float4s of A tile
            int r = f4 >> 3, cg = f4 & 7;
            float4 v = *(const float4*)&A[(m0 + r) * K + k0 + cg * 4];
            AsT[cg*4+0][r] = v.x; AsT[cg*4+1][r] = v.y;
            AsT[cg*4+2][r] = v.z; AsT[cg*4+3][r] = v.w;
        }
        #pragma unroll
        for (int i = 0; i < 2; i++) {
            int f4 = tid + i * 256;            // 512 float4s of B tile
            int kr = f4 >> 4, cg = f4 & 15;
            *(float4*)&Bs[kr][cg*4] = *(const float4*)&Bw[(k0 + kr) * N + n0 + cg * 4];
        }
        __syncthreads();
        #pragma unroll
        for (int kk = 0; kk < 32; kk++) {
            float4 a4 = *(float4*)&AsT[kk][ty * 4];
            float4 b4 = *(float4*)&Bs[kk][tx * 4];
            float av[4] = {a4.x, a4.y, a4.z, a4.w};
            float bv[4] = {b4.x, b4.y, b4.z, b4.w};
            #pragma unroll
            for (int i = 0; i < 4; i++)
                #pragma unroll
                for (int j = 0; j < 4; j++)
                    c[i][j] += av[i] * bv[j];
        }
        __syncthreads();
    }

    #pragma unroll
    for (int i = 0; i < 4; i++) {
        int row = m0 + ty * 4 + i;
        int b = row >> 11, l = row & 2047;
        #pragma unroll
        for (int j = 0; j < 4; j++) {
            int col = n0 + tx * 4 + j;
            float val = c[i][j] + bias[col];
            int t = col >> 9;                // 0=q 1=k 2=v
            int h = (col & 511) >> 6;
            int d = col & 63;
            float* dst = (t == 0) ? g_q : (t == 1) ? g_k : g_v;
            dst[((b * HH + h) * LL + l) * DD + d] = val;
        }
    }
}

// ---------------------------------------------------------------------------
// Kernel 2: block means / min-cosine / pooled softmax / CDF keep mask
// grid = B*H blocks, 256 threads
// ---------------------------------------------------------------------------
__device__ __forceinline__ void atomicMinFloat(float* addr, float val) {
    int* ia = (int*)addr;
    int old = *ia;
    while (__int_as_float(old) > val) {
        int assumed = old;
        old = atomicCAS(ia, assumed, __float_as_int(val));
        if (old == assumed) break;
    }
}

__global__ void __launch_bounds__(256) meta_mask_kernel() {
    int bh = blockIdx.x;
    const float* q = g_q + (size_t)bh * LL * DD;
    const float* k = g_k + (size_t)bh * LL * DD;
    __shared__ float qm[NQ][DD], km[NK][DD];
    __shared__ float qmnorm[NQ], kmnorm[NK];
    __shared__ float qsim[NQ], ksim[NK];
    __shared__ float pooled[NQ][NK];
    int tid = threadIdx.x;

    // block means
    for (int e = tid; e < NQ * DD; e += 256) {
        int qb = e >> 6, d = e & 63;
        float s = 0.f;
        const float* p = q + (qb * 128) * DD + d;
        for (int r = 0; r < 128; r++) s += p[r * DD];
        qm[qb][d] = s * (1.f / 128.f);
    }
    for (int e = tid; e < NK * DD; e += 256) {
        int kb = e >> 6, d = e & 63;
        float s = 0.f;
        const float* p = k + (kb * 64) * DD + d;
        for (int r = 0; r < 64; r++) s += p[r * DD];
        km[kb][d] = s * (1.f / 64.f);
    }
    if (tid < NQ) qsim[tid] = 1e30f;
    if (tid < NK) ksim[tid] = 1e30f;
    __syncthreads();

    if (tid < NQ) {
        float s = 0.f;
        for (int d = 0; d < DD; d++) s += qm[tid][d] * qm[tid][d];
        qmnorm[tid] = sqrtf(s);
    }
    if (tid < NK) {
        float s = 0.f;
        for (int d = 0; d < DD; d++) s += km[tid][d] * km[tid][d];
        kmnorm[tid] = sqrtf(s);
    }
    __syncthreads();

    // per-row cosine to block mean, min-reduced
    for (int row = tid; row < LL; row += 256) {
        int qb = row >> 7;
        const float* p = q + row * DD;
        float dot = 0.f, nn = 0.f;
        for (int d = 0; d < DD; d++) { float v = p[d]; dot += v * qm[qb][d]; nn += v * v; }
        float cosv = dot / ((sqrtf(nn) + 1e-6f) * (qmnorm[qb] + 1e-6f));
        atomicMinFloat(&qsim[qb], cosv);
    }
    for (int row = tid; row < LL; row += 256) {
        int kb = row >> 6;
        const float* p = k + row * DD;
        float dot = 0.f, nn = 0.f;
        for (int d = 0; d < DD; d++) { float v = p[d]; dot += v * km[kb][d]; nn += v * v; }
        float cosv = dot / ((sqrtf(nn) + 1e-6f) * (kmnorm[kb] + 1e-6f));
        atomicMinFloat(&ksim[kb], cosv);
    }
    __syncthreads();

    // pooled logits
    for (int e = tid; e < NQ * NK; e += 256) {
        int qi = e >> 5, ki = e & 31;
        float dot = 0.f;
        for (int d = 0; d < DD; d++) dot += qm[qi][d] * km[ki][d];
        pooled[qi][ki] = dot * SCALE;
    }
    __syncthreads();

    // per-Q-block-row: softmax, stable descending sort, CDF keep, write mask
    if (tid < NQ) {
        float vals[NK]; int idx[NK];
        float mx = -CUDART_INF_F;
        for (int i = 0; i < NK; i++) mx = fmaxf(mx, pooled[tid][i]);
        float sum = 0.f;
        for (int i = 0; i < NK; i++) { vals[i] = expf(pooled[tid][i] - mx); sum += vals[i]; }
        float inv = 1.f / sum;
        for (int i = 0; i < NK; i++) { vals[i] *= inv; idx[i] = i; }
        // stable insertion sort, descending
        for (int i = 1; i < NK; i++) {
            float kv = vals[i]; int ki = idx[i];
            int j = i - 1;
            while (j >= 0 && vals[j] < kv) { vals[j+1] = vals[j]; idx[j+1] = idx[j]; j--; }
            vals[j+1] = kv; idx[j+1] = ki;
        }
        unsigned keep = 0u;
        float csum = 0.f;
        for (int i = 0; i < NK; i++) {
            if (csum < CDFTH) keep |= (1u << idx[i]);
            csum += vals[i];
        }
        bool qself = qsim[tid] > SIMTH;
        int* mrow = g_mask + (bh * NQ + tid) * NK;
        for (int ki = 0; ki < NK; ki++) {
            bool kself = ksim[ki] > SIMTH;
            mrow[ki] = (((keep >> ki) & 1u) || !qself || !kself) ? 1 : 0;
        }
    }
}

// ---------------------------------------------------------------------------
// Kernel 3: block-sparse flash attention
// grid = (nq=16, B*H=16), 128 threads (one thread per query row)
// ---------------------------------------------------------------------------
__global__ void __launch_bounds__(128, 1) attn_kernel() {
    int qb = blockIdx.x;
    int bh = blockIdx.y;
    int b = bh >> 3, h = bh & 7;
    int tid = threadIdx.x;

    __shared__ float Ks[64][64];
    __shared__ float Vs[64][64];

    const float* qptr = g_q + ((size_t)bh * LL + qb * 128 + tid) * DD;
    float qreg[DD];
    #pragma unroll
    for (int d = 0; d < DD; d += 4) *(float4*)&qreg[d] = *(const float4*)&qptr[d];

    float acc[DD];
    #pragma unroll
    for (int d = 0; d < DD; d++) acc[d] = 0.f;
    float mrun = -CUDART_INF_F, lrun = 0.f;

    const int* mrow = g_mask + (bh * NQ + qb) * NK;

    for (int kb = 0; kb < NK; kb++) {
        if (!mrow[kb]) continue;   // uniform across block
        const float* kp = g_k + ((size_t)bh * LL + kb * 64) * DD;
        const float* vp = g_v + ((size_t)bh * LL + kb * 64) * DD;
        #pragma unroll
        for (int i = 0; i < 8; i++) {
            int f4 = tid + i * 128;        // 1024 float4s
            int r = f4 >> 4, cg = f4 & 15;
            *(float4*)&Ks[r][cg*4] = *(const float4*)&kp[r * DD + cg * 4];
            *(float4*)&Vs[r][cg*4] = *(const float4*)&vp[r * DD + cg * 4];
        }
        __syncthreads();

        #pragma unroll
        for (int half = 0; half < 2; half++) {
            float s[32];
            float tmax = -CUDART_INF_F;
            #pragma unroll
            for (int j = 0; j < 32; j++) {
                const float* kr = &Ks[half * 32 + j][0];
                float dot = 0.f;
                #pragma unroll
                for (int d = 0; d < DD; d++) dot += qreg[d] * kr[d];
                s[j] = dot * SCALE;
                tmax = fmaxf(tmax, s[j]);
            }
            float newm = fmaxf(mrun, tmax);
            float corr = __expf(mrun - newm);
            lrun *= corr;
            #pragma unroll
            for (int d = 0; d < DD; d++) acc[d] *= corr;
            #pragma unroll
            for (int j = 0; j < 32; j++) {
                float p = __expf(s[j] - newm);
                lrun += p;
                const float* vr = &Vs[half * 32 + j][0];
                #pragma unroll
                for (int d = 0; d < DD; d++) acc[d] += p * vr[d];
            }
            mrun = newm;
        }
        __syncthreads();
    }

    float inv = 1.f / lrun;
    int row = qb * 128 + tid;
    float* op = g_o + ((size_t)b * LL + row) * CC + h * DD;
    #pragma unroll
    for (int d = 0; d < DD; d += 4) {
        float4 o4;
        o4.x = acc[d+0] * inv; o4.y = acc[d+1] * inv;
        o4.z = acc[d+2] * inv; o4.w = acc[d+3] * inv;
        *(float4*)&op[d] = o4;
    }
}

// ---------------------------------------------------------------------------
// Kernel 4: output projection  g_o[4096,512] @ Wproj[512,512] + bproj -> out
// ---------------------------------------------------------------------------
__global__ void __launch_bounds__(256) sgemm_proj(const float* __restrict__ Bw,
                                                  const float* __restrict__ bias,
                                                  float* __restrict__ out) {
    const int K = CC, N = CC;
    int m0 = blockIdx.y * 64, n0 = blockIdx.x * 64;
    __shared__ float AsT[32][68];
    __shared__ float Bs[32][64];
    int tid = threadIdx.x;
    int tx = tid & 15, ty = tid >> 4;
    float c[4][4] = {};
    const float* A = g_o;

    for (int k0 = 0; k0 < K; k0 += 32) {
        #pragma unroll
        for (int i = 0; i < 2; i++) {
            int f4 = tid + i * 256;
            int r = f4 >> 3, cg = f4 & 7;
            float4 v = *(const float4*)&A[(m0 + r) * K + k0 + cg * 4];
            AsT[cg*4+0][r] = v.x; AsT[cg*4+1][r] = v.y;
            AsT[cg*4+2][r] = v.z; AsT[cg*4+3][r] = v.w;
        }
        #pragma unroll
        for (int i = 0; i < 2; i++) {
            int f4 = tid + i * 256;
            int kr = f4 >> 4, cg = f4 & 15;
            *(float4*)&Bs[kr][cg*4] = *(const float4*)&Bw[(k0 + kr) * N + n0 + cg * 4];
        }
        __syncthreads();
        #pragma unroll
        for (int kk = 0; kk < 32; kk++) {
            float4 a4 = *(float4*)&AsT[kk][ty * 4];
            float4 b4 = *(float4*)&Bs[kk][tx * 4];
            float av[4] = {a4.x, a4.y, a4.z, a4.w};
            float bv[4] = {b4.x, b4.y, b4.z, b4.w};
            #pragma unroll
            for (int i = 0; i < 4; i++)
                #pragma unroll
                for (int j = 0; j < 4; j++)
                    c[i][j] += av[i] * bv[j];
        }
        __syncthreads();
    }

    #pragma unroll
    for (int i = 0; i < 4; i++) {
        int row = m0 + ty * 4 + i;
        #pragma unroll
        for (int j = 0; j < 4; j++) {
            int col = n0 + tx * 4 + j;
            out[row * N + col] = c[i][j] + bias[col];
        }
    }
}

// ---------------------------------------------------------------------------
extern "C" void kernel_launch(void* const* d_in, const int* in_sizes, int n_in,
                              void* d_out, int out_size) {
    const float* x     = (const float*)d_in[0];
    const float* Wqkv  = (const float*)d_in[1];
    const float* bqkv  = (const float*)d_in[2];
    const float* Wproj = (const float*)d_in[3];
    const float* bproj = (const float*)d_in[4];
    float* out = (float*)d_out;

    sgemm_qkv<<<dim3(NQKV / 64, MM / 64), 256>>>(x, Wqkv, bqkv);
    meta_mask_kernel<<<BB * HH, 256>>>();
    attn_kernel<<<dim3(NQ, BB * HH), 128>>>();
    sgemm_proj<<<dim3(CC / 64, MM / 64), 256>>>(Wproj, bproj, out);
}

// round 6
// speedup vs baseline: 2.3446x; 2.3446x over previous
#include <cuda_runtime.h>
#include <cuda_bf16.h>
#include <math_constants.h>

// Problem constants
#define BB   2
#define LL   2048
#define CC   512
#define HH   8
#define DD   64
#define MM   (BB*LL)          // 4096 rows
#define NQKV (3*CC)           // 1536
#define NQ   16               // L/128 (mask Q-block granularity)
#define NK   32               // L/64
#define SCALE 0.125f          // D^-0.5
#define SIMTH 0.6f
#define CDFTH 0.98f

// Scratch (allocation-free rule -> device globals)
__device__ float g_q[BB*HH*LL*DD];     // [B,H,L,D]
__device__ float g_k[BB*HH*LL*DD];
__device__ float g_v[BB*HH*LL*DD];
__device__ float g_o[BB*LL*CC];        // [B,L,C]
__device__ int   g_mask[BB*HH*NQ*NK];  // 1 = keep block

// ---------------------------------------------------------------------------
// Kernel 1: QKV GEMM  (x[4096,512] @ Wqkv[512,1536] + bqkv) scattered to q/k/v
// ---------------------------------------------------------------------------
__global__ void __launch_bounds__(256) sgemm_qkv(const float* __restrict__ A,
                                                 const float* __restrict__ Bw,
                                                 const float* __restrict__ bias) {
    const int K = CC, N = NQKV;
    int m0 = blockIdx.y * 64, n0 = blockIdx.x * 64;
    __shared__ float AsT[32][68];
    __shared__ float Bs[32][64];
    int tid = threadIdx.x;
    int tx = tid & 15, ty = tid >> 4;
    float c[4][4] = {};

    for (int k0 = 0; k0 < K; k0 += 32) {
        #pragma unroll
        for (int i = 0; i < 2; i++) {
            int f4 = tid + i * 256;
            int r = f4 >> 3, cg = f4 & 7;
            float4 v = *(const float4*)&A[(m0 + r) * K + k0 + cg * 4];
            AsT[cg*4+0][r] = v.x; AsT[cg*4+1][r] = v.y;
            AsT[cg*4+2][r] = v.z; AsT[cg*4+3][r] = v.w;
        }
        #pragma unroll
        for (int i = 0; i < 2; i++) {
            int f4 = tid + i * 256;
            int kr = f4 >> 4, cg = f4 & 15;
            *(float4*)&Bs[kr][cg*4] = *(const float4*)&Bw[(k0 + kr) * N + n0 + cg * 4];
        }
        __syncthreads();
        #pragma unroll
        for (int kk = 0; kk < 32; kk++) {
            float4 a4 = *(float4*)&AsT[kk][ty * 4];
            float4 b4 = *(float4*)&Bs[kk][tx * 4];
            float av[4] = {a4.x, a4.y, a4.z, a4.w};
            float bv[4] = {b4.x, b4.y, b4.z, b4.w};
            #pragma unroll
            for (int i = 0; i < 4; i++)
                #pragma unroll
                for (int j = 0; j < 4; j++)
                    c[i][j] += av[i] * bv[j];
        }
        __syncthreads();
    }

    #pragma unroll
    for (int i = 0; i < 4; i++) {
        int row = m0 + ty * 4 + i;
        int b = row >> 11, l = row & 2047;
        #pragma unroll
        for (int j = 0; j < 4; j++) {
            int col = n0 + tx * 4 + j;
            float val = c[i][j] + bias[col];
            int t = col >> 9;
            int h = (col & 511) >> 6;
            int d = col & 63;
            float* dst = (t == 0) ? g_q : (t == 1) ? g_k : g_v;
            dst[((b * HH + h) * LL + l) * DD + d] = val;
        }
    }
}

// ---------------------------------------------------------------------------
// Kernel 2: block means / min-cosine / pooled softmax / CDF keep mask (fp32)
// ---------------------------------------------------------------------------
__device__ __forceinline__ void atomicMinFloat(float* addr, float val) {
    int* ia = (int*)addr;
    int old = *ia;
    while (__int_as_float(old) > val) {
        int assumed = old;
        old = atomicCAS(ia, assumed, __float_as_int(val));
        if (old == assumed) break;
    }
}

__global__ void __launch_bounds__(256) meta_mask_kernel() {
    int bh = blockIdx.x;
    const float* q = g_q + (size_t)bh * LL * DD;
    const float* k = g_k + (size_t)bh * LL * DD;
    __shared__ float qm[NQ][DD], km[NK][DD];
    __shared__ float qmnorm[NQ], kmnorm[NK];
    __shared__ float qsim[NQ], ksim[NK];
    __shared__ float pooled[NQ][NK];
    int tid = threadIdx.x;

    for (int e = tid; e < NQ * DD; e += 256) {
        int qb = e >> 6, d = e & 63;
        float s = 0.f;
        const float* p = q + (qb * 128) * DD + d;
        for (int r = 0; r < 128; r++) s += p[r * DD];
        qm[qb][d] = s * (1.f / 128.f);
    }
    for (int e = tid; e < NK * DD; e += 256) {
        int kb = e >> 6, d = e & 63;
        float s = 0.f;
        const float* p = k + (kb * 64) * DD + d;
        for (int r = 0; r < 64; r++) s += p[r * DD];
        km[kb][d] = s * (1.f / 64.f);
    }
    if (tid < NQ) qsim[tid] = 1e30f;
    if (tid < NK) ksim[tid] = 1e30f;
    __syncthreads();

    if (tid < NQ) {
        float s = 0.f;
        for (int d = 0; d < DD; d++) s += qm[tid][d] * qm[tid][d];
        qmnorm[tid] = sqrtf(s);
    }
    if (tid < NK) {
        float s = 0.f;
        for (int d = 0; d < DD; d++) s += km[tid][d] * km[tid][d];
        kmnorm[tid] = sqrtf(s);
    }
    __syncthreads();

    for (int row = tid; row < LL; row += 256) {
        int qb = row >> 7;
        const float* p = q + row * DD;
        float dot = 0.f, nn = 0.f;
        for (int d = 0; d < DD; d++) { float v = p[d]; dot += v * qm[qb][d]; nn += v * v; }
        float cosv = dot / ((sqrtf(nn) + 1e-6f) * (qmnorm[qb] + 1e-6f));
        atomicMinFloat(&qsim[qb], cosv);
    }
    for (int row = tid; row < LL; row += 256) {
        int kb = row >> 6;
        const float* p = k + row * DD;
        float dot = 0.f, nn = 0.f;
        for (int d = 0; d < DD; d++) { float v = p[d]; dot += v * km[kb][d]; nn += v * v; }
        float cosv = dot / ((sqrtf(nn) + 1e-6f) * (kmnorm[kb] + 1e-6f));
        atomicMinFloat(&ksim[kb], cosv);
    }
    __syncthreads();

    for (int e = tid; e < NQ * NK; e += 256) {
        int qi = e >> 5, ki = e & 31;
        float dot = 0.f;
        for (int d = 0; d < DD; d++) dot += qm[qi][d] * km[ki][d];
        pooled[qi][ki] = dot * SCALE;
    }
    __syncthreads();

    if (tid < NQ) {
        float vals[NK]; int idx[NK];
        float mx = -CUDART_INF_F;
        for (int i = 0; i < NK; i++) mx = fmaxf(mx, pooled[tid][i]);
        float sum = 0.f;
        for (int i = 0; i < NK; i++) { vals[i] = expf(pooled[tid][i] - mx); sum += vals[i]; }
        float inv = 1.f / sum;
        for (int i = 0; i < NK; i++) { vals[i] *= inv; idx[i] = i; }
        for (int i = 1; i < NK; i++) {
            float kv = vals[i]; int ki = idx[i];
            int j = i - 1;
            while (j >= 0 && vals[j] < kv) { vals[j+1] = vals[j]; idx[j+1] = idx[j]; j--; }
            vals[j+1] = kv; idx[j+1] = ki;
        }
        unsigned keep = 0u;
        float csum = 0.f;
        for (int i = 0; i < NK; i++) {
            if (csum < CDFTH) keep |= (1u << idx[i]);
            csum += vals[i];
        }
        bool qself = qsim[tid] > SIMTH;
        int* mrow = g_mask + (bh * NQ + tid) * NK;
        for (int ki = 0; ki < NK; ki++) {
            bool kself = ksim[ki] > SIMTH;
            mrow[ki] = (((keep >> ki) & 1u) || !qself || !kself) ? 1 : 0;
        }
    }
}

// ---------------------------------------------------------------------------
// Kernel 3: block-sparse flash attention, tf32 mma.sync (m16n8k8)
// grid = (32 q-tiles of 64 rows, 16 bh), 128 threads = 4 warps x 16 rows
// Dynamic smem: Qs[64][68] | Ks[64][68] | Vs[64][68] | Ps[4 warps][16][68]
// All mma operands are conflict-free scalar LDS from row-major stride-68 smem.
// ---------------------------------------------------------------------------
#define AT_S 68
#define ATT_SMEM_FLOATS (3*64*AT_S + 4*16*AT_S)
#define ATT_SMEM_BYTES  (ATT_SMEM_FLOATS * 4)

__device__ __forceinline__ unsigned f2tf32(float x) {
    unsigned r;
    asm("cvt.rna.tf32.f32 %0, %1;" : "=r"(r) : "f"(x));
    return r;
}

__device__ __forceinline__ void mma_tf32(float c[4],
                                         unsigned a0, unsigned a1, unsigned a2, unsigned a3,
                                         unsigned b0, unsigned b1) {
    asm volatile(
        "mma.sync.aligned.m16n8k8.row.col.f32.tf32.tf32.f32 "
        "{%0,%1,%2,%3}, {%4,%5,%6,%7}, {%8,%9}, {%0,%1,%2,%3};"
        : "+f"(c[0]), "+f"(c[1]), "+f"(c[2]), "+f"(c[3])
        : "r"(a0), "r"(a1), "r"(a2), "r"(a3), "r"(b0), "r"(b1));
}

extern __shared__ float sm_attn[];

__global__ void __launch_bounds__(128) attn_tf32() {
    const int qb = blockIdx.x;          // 64-row q tile (0..31)
    const int bh = blockIdx.y;          // 0..15
    const int b = bh >> 3, h = bh & 7;
    const int tid  = threadIdx.x;
    const int wid  = tid >> 5;
    const int lane = tid & 31;
    const int lr = lane >> 2;           // fragment group row 0..7
    const int lc = lane & 3;            // fragment group col 0..3

    float* Qs = sm_attn;                      // [64][68]
    float* Ks = Qs + 64 * AT_S;               // [64][68]
    float* Vs = Ks + 64 * AT_S;               // [64][68]
    float* Ps = Vs + 64 * AT_S + wid * 16 * AT_S;  // per-warp [16][68]

    // Stage Q (pre-scaled, tf32-rounded)
    const float* qg = g_q + ((size_t)bh * LL + qb * 64) * DD;
    for (int i = tid; i < 1024; i += 128) {
        int r = i >> 4, dg = i & 15;
        float4 v = *(const float4*)&qg[r * DD + dg * 4];
        float4 w;
        w.x = __uint_as_float(f2tf32(v.x * SCALE));
        w.y = __uint_as_float(f2tf32(v.y * SCALE));
        w.z = __uint_as_float(f2tf32(v.z * SCALE));
        w.w = __uint_as_float(f2tf32(v.w * SCALE));
        *(float4*)&Qs[r * AT_S + dg * 4] = w;
    }

    float o[8][4];
    #pragma unroll
    for (int nt = 0; nt < 8; nt++)
        #pragma unroll
        for (int j = 0; j < 4; j++) o[nt][j] = 0.f;
    float m0r = -CUDART_INF_F, m1r = -CUDART_INF_F;
    float l0 = 0.f, l1 = 0.f;

    const int* mrow = g_mask + (bh * NQ + (qb >> 1)) * NK;  // mask Q blocks are 128 rows
    const float* kg = g_k + (size_t)bh * LL * DD;
    const float* vg = g_v + (size_t)bh * LL * DD;
    const float* Qw = Qs + (wid * 16) * AT_S;

    for (int kb = 0; kb < NK; kb++) {
        if (!mrow[kb]) continue;       // uniform across block
        __syncthreads();               // previous PV reads of Ks/Vs done

        // Stage K, V tiles (tf32-rounded)
        const float* kp = kg + (size_t)(kb * 64) * DD;
        const float* vp = vg + (size_t)(kb * 64) * DD;
        for (int i = tid; i < 1024; i += 128) {
            int r = i >> 4, dg = i & 15;
            float4 kv = *(const float4*)&kp[r * DD + dg * 4];
            float4 vv = *(const float4*)&vp[r * DD + dg * 4];
            float4 kw, vw;
            kw.x = __uint_as_float(f2tf32(kv.x)); kw.y = __uint_as_float(f2tf32(kv.y));
            kw.z = __uint_as_float(f2tf32(kv.z)); kw.w = __uint_as_float(f2tf32(kv.w));
            vw.x = __uint_as_float(f2tf32(vv.x)); vw.y = __uint_as_float(f2tf32(vv.y));
            vw.z = __uint_as_float(f2tf32(vv.z)); vw.w = __uint_as_float(f2tf32(vv.w));
            *(float4*)&Ks[r * AT_S + dg * 4] = kw;
            *(float4*)&Vs[r * AT_S + dg * 4] = vw;
        }
        __syncthreads();

        // S = Q K^T : warp computes 16 q rows x 64 kpos (Q already has SCALE)
        float sc[8][4];
        #pragma unroll
        for (int nt = 0; nt < 8; nt++)
            #pragma unroll
            for (int j = 0; j < 4; j++) sc[nt][j] = 0.f;

        #pragma unroll
        for (int kk = 0; kk < 8; kk++) {
            int k0 = kk * 8;
            unsigned a0 = __float_as_uint(Qw[(lr    ) * AT_S + k0 + lc    ]);
            unsigned a1 = __float_as_uint(Qw[(lr + 8) * AT_S + k0 + lc    ]);
            unsigned a2 = __float_as_uint(Qw[(lr    ) * AT_S + k0 + lc + 4]);
            unsigned a3 = __float_as_uint(Qw[(lr + 8) * AT_S + k0 + lc + 4]);
            #pragma unroll
            for (int nt = 0; nt < 8; nt++) {
                unsigned b0 = __float_as_uint(Ks[(nt * 8 + lr) * AT_S + k0 + lc    ]);
                unsigned b1 = __float_as_uint(Ks[(nt * 8 + lr) * AT_S + k0 + lc + 4]);
                mma_tf32(sc[nt], a0, a1, a2, a3, b0, b1);
            }
        }

        // Online softmax update (rows lr and lr+8 of the warp's 16)
        float rl = -CUDART_INF_F, rh = -CUDART_INF_F;
        #pragma unroll
        for (int nt = 0; nt < 8; nt++) {
            rl = fmaxf(rl, fmaxf(sc[nt][0], sc[nt][1]));
            rh = fmaxf(rh, fmaxf(sc[nt][2], sc[nt][3]));
        }
        rl = fmaxf(rl, __shfl_xor_sync(0xffffffffu, rl, 1));
        rl = fmaxf(rl, __shfl_xor_sync(0xffffffffu, rl, 2));
        rh = fmaxf(rh, __shfl_xor_sync(0xffffffffu, rh, 1));
        rh = fmaxf(rh, __shfl_xor_sync(0xffffffffu, rh, 2));
        float mn0 = fmaxf(m0r, rl), mn1 = fmaxf(m1r, rh);
        float c0 = __expf(m0r - mn0), c1 = __expf(m1r - mn1);
        float s0 = 0.f, s1 = 0.f;
        #pragma unroll
        for (int nt = 0; nt < 8; nt++) {
            float p0 = __expf(sc[nt][0] - mn0);
            float p1 = __expf(sc[nt][1] - mn0);
            float p2 = __expf(sc[nt][2] - mn1);
            float p3 = __expf(sc[nt][3] - mn1);
            s0 += p0 + p1; s1 += p2 + p3;
            o[nt][0] *= c0; o[nt][1] *= c0;
            o[nt][2] *= c1; o[nt][3] *= c1;
            uint2 wlo = make_uint2(f2tf32(p0), f2tf32(p1));
            uint2 whi = make_uint2(f2tf32(p2), f2tf32(p3));
            *(uint2*)&Ps[(lr    ) * AT_S + nt * 8 + 2 * lc] = wlo;
            *(uint2*)&Ps[(lr + 8) * AT_S + nt * 8 + 2 * lc] = whi;
        }
        s0 += __shfl_xor_sync(0xffffffffu, s0, 1);
        s0 += __shfl_xor_sync(0xffffffffu, s0, 2);
        s1 += __shfl_xor_sync(0xffffffffu, s1, 1);
        s1 += __shfl_xor_sync(0xffffffffu, s1, 2);
        l0 = l0 * c0 + s0;
        l1 = l1 * c1 + s1;
        m0r = mn0; m1r = mn1;
        __syncwarp();

        // O += P @ V (P is warp-private in smem)
        #pragma unroll
        for (int kk = 0; kk < 8; kk++) {
            int k0 = kk * 8;
            unsigned a0 = __float_as_uint(Ps[(lr    ) * AT_S + k0 + lc    ]);
            unsigned a1 = __float_as_uint(Ps[(lr + 8) * AT_S + k0 + lc    ]);
            unsigned a2 = __float_as_uint(Ps[(lr    ) * AT_S + k0 + lc + 4]);
            unsigned a3 = __float_as_uint(Ps[(lr + 8) * AT_S + k0 + lc + 4]);
            #pragma unroll
            for (int nt = 0; nt < 8; nt++) {
                unsigned b0 = __float_as_uint(Vs[(k0 + lc    ) * AT_S + nt * 8 + lr]);
                unsigned b1 = __float_as_uint(Vs[(k0 + lc + 4) * AT_S + nt * 8 + lr]);
                mma_tf32(o[nt], a0, a1, a2, a3, b0, b1);
            }
        }
    }

    // Epilogue: normalize and scatter to g_o
    float inv0 = 1.f / l0, inv1 = 1.f / l1;
    int r0 = qb * 64 + wid * 16 + lr;
    float* og = g_o + (size_t)b * LL * CC + h * DD;
    #pragma unroll
    for (int nt = 0; nt < 8; nt++) {
        float2 w0 = make_float2(o[nt][0] * inv0, o[nt][1] * inv0);
        float2 w1 = make_float2(o[nt][2] * inv1, o[nt][3] * inv1);
        *(float2*)&og[(size_t)(r0    ) * CC + nt * 8 + 2 * lc] = w0;
        *(float2*)&og[(size_t)(r0 + 8) * CC + nt * 8 + 2 * lc] = w1;
    }
}

// ---------------------------------------------------------------------------
// Kernel 4: output projection  g_o[4096,512] @ Wproj[512,512] + bproj -> out
// ---------------------------------------------------------------------------
__global__ void __launch_bounds__(256) sgemm_proj(const float* __restrict__ Bw,
                                                  const float* __restrict__ bias,
                                                  float* __restrict__ out) {
    const int K = CC, N = CC;
    int m0 = blockIdx.y * 64, n0 = blockIdx.x * 64;
    __shared__ float AsT[32][68];
    __shared__ float Bs[32][64];
    int tid = threadIdx.x;
    int tx = tid & 15, ty = tid >> 4;
    float c[4][4] = {};
    const float* A = g_o;

    for (int k0 = 0; k0 < K; k0 += 32) {
        #pragma unroll
        for (int i = 0; i < 2; i++) {
            int f4 = tid + i * 256;
            int r = f4 >> 3, cg = f4 & 7;
            float4 v = *(const float4*)&A[(m0 + r) * K + k0 + cg * 4];
            AsT[cg*4+0][r] = v.x; AsT[cg*4+1][r] = v.y;
            AsT[cg*4+2][r] = v.z; AsT[cg*4+3][r] = v.w;
        }
        #pragma unroll
        for (int i = 0; i < 2; i++) {
            int f4 = tid + i * 256;
            int kr = f4 >> 4, cg = f4 & 15;
            *(float4*)&Bs[kr][cg*4] = *(const float4*)&Bw[(k0 + kr) * N + n0 + cg * 4];
        }
        __syncthreads();
        #pragma unroll
        for (int kk = 0; kk < 32; kk++) {
            float4 a4 = *(float4*)&AsT[kk][ty * 4];
            float4 b4 = *(float4*)&Bs[kk][tx * 4];
            float av[4] = {a4.x, a4.y, a4.z, a4.w};
            float bv[4] = {b4.x, b4.y, b4.z, b4.w};
            #pragma unroll
            for (int i = 0; i < 4; i++)
                #pragma unroll
                for (int j = 0; j < 4; j++)
                    c[i][j] += av[i] * bv[j];
        }
        __syncthreads();
    }

    #pragma unroll
    for (int i = 0; i < 4; i++) {
        int row = m0 + ty * 4 + i;
        #pragma unroll
        for (int j = 0; j < 4; j++) {
            int col = n0 + tx * 4 + j;
            out[row * N + col] = c[i][j] + bias[col];
        }
    }
}

// ---------------------------------------------------------------------------
extern "C" void kernel_launch(void* const* d_in, const int* in_sizes, int n_in,
                              void* d_out, int out_size) {
    const float* x     = (const float*)d_in[0];
    const float* Wqkv  = (const float*)d_in[1];
    const float* bqkv  = (const float*)d_in[2];
    const float* Wproj = (const float*)d_in[3];
    const float* bproj = (const float*)d_in[4];
    float* out = (float*)d_out;

    cudaFuncSetAttribute(attn_tf32, cudaFuncAttributeMaxDynamicSharedMemorySize,
                         ATT_SMEM_BYTES);

    sgemm_qkv<<<dim3(NQKV / 64, MM / 64), 256>>>(x, Wqkv, bqkv);
    meta_mask_kernel<<<BB * HH, 256>>>();
    attn_tf32<<<dim3(32, BB * HH), 128, ATT_SMEM_BYTES>>>();
    sgemm_proj<<<dim3(CC / 64, MM / 64), 256>>>(Wproj, bproj, out);
}

// round 7
// speedup vs baseline: 3.0065x; 1.2823x over previous
#include <cuda_runtime.h>
#include <cuda_bf16.h>
#include <math_constants.h>

// Problem constants
#define BB   2
#define LL   2048
#define CC   512
#define HH   8
#define DD   64
#define MM   (BB*LL)          // 4096 rows
#define NQKV (3*CC)           // 1536
#define NQ   16               // L/128 (mask Q-block granularity)
#define NK   32               // L/64
#define SCALE 0.125f          // D^-0.5
#define SIMTH 0.6f
#define CDFTH 0.98f

// Scratch (allocation-free rule -> device globals)
__device__ float g_q[BB*HH*LL*DD];     // [B,H,L,D]
__device__ float g_k[BB*HH*LL*DD];
__device__ float g_v[BB*HH*LL*DD];
__device__ float g_o[BB*LL*CC];        // [B,L,C]
__device__ int   g_mask[BB*HH*NQ*NK];  // 1 = keep block

__device__ __forceinline__ unsigned f2tf32(float x) {
    unsigned r;
    asm("cvt.rna.tf32.f32 %0, %1;" : "=r"(r) : "f"(x));
    return r;
}

__device__ __forceinline__ void mma_tf32(float c[4],
                                         unsigned a0, unsigned a1, unsigned a2, unsigned a3,
                                         unsigned b0, unsigned b1) {
    asm volatile(
        "mma.sync.aligned.m16n8k8.row.col.f32.tf32.tf32.f32 "
        "{%0,%1,%2,%3}, {%4,%5,%6,%7}, {%8,%9}, {%0,%1,%2,%3};"
        : "+f"(c[0]), "+f"(c[1]), "+f"(c[2]), "+f"(c[3])
        : "r"(a0), "r"(a1), "r"(a2), "r"(a3), "r"(b0), "r"(b1));
}

// ---------------------------------------------------------------------------
// tf32 tensor-core GEMM: C[M,N] = A[M,K=512] @ B[K,N] + bias
// 128x64 block tile, 256 threads = 8 warps (4 M x 2 N), warp tile 32x32.
// SCATTER=true: A = x, output scattered to g_q/g_k/g_v (qkv layout).
// SCATTER=false: A = g_o, output written dense to `out`.
// ---------------------------------------------------------------------------
template<int N, bool SCATTER>
__global__ void __launch_bounds__(256) gemm_tf32(const float* __restrict__ A,
                                                 const float* __restrict__ Bw,
                                                 const float* __restrict__ bias,
                                                 float* __restrict__ out) {
    const int K = CC;
    const float* Ap = SCATTER ? A : (const float*)g_o;
    int m0 = blockIdx.y * 128, n0 = blockIdx.x * 64;
    __shared__ float As[128 * 36];     // A tile, stride 36 (conflict-free frags)
    __shared__ float BsT[64 * 36];     // B tile transposed [n][k]
    int tid = threadIdx.x;
    int wid = tid >> 5, lane = tid & 31;
    int lr = lane >> 2, lc = lane & 3;
    int warp_m = wid & 3, warp_n = wid >> 2;

    float c[2][4][4] = {};

    for (int k0 = 0; k0 < K; k0 += 32) {
        // Stage A tile 128x32 (tf32-rounded)
        #pragma unroll
        for (int i = 0; i < 4; i++) {
            int f4 = tid + i * 256;
            int r = f4 >> 3, cg = f4 & 7;
            float4 v = *(const float4*)&Ap[(size_t)(m0 + r) * K + k0 + cg * 4];
            float4 w;
            w.x = __uint_as_float(f2tf32(v.x)); w.y = __uint_as_float(f2tf32(v.y));
            w.z = __uint_as_float(f2tf32(v.z)); w.w = __uint_as_float(f2tf32(v.w));
            *(float4*)&As[r * 36 + cg * 4] = w;
        }
        // Stage B tile 32x64, transposed into BsT[64][32]
        #pragma unroll
        for (int i = 0; i < 2; i++) {
            int f4 = tid + i * 256;
            int kr = f4 >> 4, ng = f4 & 15;
            float4 v = *(const float4*)&Bw[(size_t)(k0 + kr) * N + n0 + ng * 4];
            BsT[(ng * 4 + 0) * 36 + kr] = __uint_as_float(f2tf32(v.x));
            BsT[(ng * 4 + 1) * 36 + kr] = __uint_as_float(f2tf32(v.y));
            BsT[(ng * 4 + 2) * 36 + kr] = __uint_as_float(f2tf32(v.z));
            BsT[(ng * 4 + 3) * 36 + kr] = __uint_as_float(f2tf32(v.w));
        }
        __syncthreads();

        const float* Aw = As + (warp_m * 32) * 36;
        const float* Bt = BsT + (warp_n * 32) * 36;
        #pragma unroll
        for (int kk = 0; kk < 4; kk++) {
            int kf = kk * 8;
            unsigned a[2][4];
            #pragma unroll
            for (int mt = 0; mt < 2; mt++) {
                a[mt][0] = __float_as_uint(Aw[(mt * 16 + lr    ) * 36 + kf + lc    ]);
                a[mt][1] = __float_as_uint(Aw[(mt * 16 + lr + 8) * 36 + kf + lc    ]);
                a[mt][2] = __float_as_uint(Aw[(mt * 16 + lr    ) * 36 + kf + lc + 4]);
                a[mt][3] = __float_as_uint(Aw[(mt * 16 + lr + 8) * 36 + kf + lc + 4]);
            }
            unsigned bf[4][2];
            #pragma unroll
            for (int nt = 0; nt < 4; nt++) {
                bf[nt][0] = __float_as_uint(Bt[(nt * 8 + lr) * 36 + kf + lc    ]);
                bf[nt][1] = __float_as_uint(Bt[(nt * 8 + lr) * 36 + kf + lc + 4]);
            }
            #pragma unroll
            for (int mt = 0; mt < 2; mt++)
                #pragma unroll
                for (int nt = 0; nt < 4; nt++)
                    mma_tf32(c[mt][nt], a[mt][0], a[mt][1], a[mt][2], a[mt][3],
                             bf[nt][0], bf[nt][1]);
        }
        __syncthreads();
    }

    // Epilogue (fp32 bias add)
    #pragma unroll
    for (int mt = 0; mt < 2; mt++) {
        #pragma unroll
        for (int half = 0; half < 2; half++) {
            int row = m0 + warp_m * 32 + mt * 16 + lr + half * 8;
            #pragma unroll
            for (int nt = 0; nt < 4; nt++) {
                int col = n0 + warp_n * 32 + nt * 8 + 2 * lc;
                float v0 = c[mt][nt][half * 2 + 0] + bias[col];
                float v1 = c[mt][nt][half * 2 + 1] + bias[col + 1];
                if (SCATTER) {
                    int b = row >> 11, l = row & 2047;
                    int t = col >> 9;
                    int h = (col & 511) >> 6;
                    int d = col & 63;
                    float* dst = (t == 0) ? g_q : (t == 1) ? g_k : g_v;
                    *(float2*)&dst[((size_t)(b * HH + h) * LL + l) * DD + d] =
                        make_float2(v0, v1);
                } else {
                    *(float2*)&out[(size_t)row * N + col] = make_float2(v0, v1);
                }
            }
        }
    }
}

// ---------------------------------------------------------------------------
// Kernel 2: block means / min-cosine / pooled softmax / CDF keep mask (fp32)
// ---------------------------------------------------------------------------
__device__ __forceinline__ void atomicMinFloat(float* addr, float val) {
    int* ia = (int*)addr;
    int old = *ia;
    while (__int_as_float(old) > val) {
        int assumed = old;
        old = atomicCAS(ia, assumed, __float_as_int(val));
        if (old == assumed) break;
    }
}

__global__ void __launch_bounds__(256) meta_mask_kernel() {
    int bh = blockIdx.x;
    const float* q = g_q + (size_t)bh * LL * DD;
    const float* k = g_k + (size_t)bh * LL * DD;
    __shared__ float qm[NQ][DD], km[NK][DD];
    __shared__ float qmnorm[NQ], kmnorm[NK];
    __shared__ float qsim[NQ], ksim[NK];
    __shared__ float pooled[NQ][NK];
    int tid = threadIdx.x;

    for (int e = tid; e < NQ * DD; e += 256) {
        int qb = e >> 6, d = e & 63;
        float s = 0.f;
        const float* p = q + (qb * 128) * DD + d;
        for (int r = 0; r < 128; r++) s += p[r * DD];
        qm[qb][d] = s * (1.f / 128.f);
    }
    for (int e = tid; e < NK * DD; e += 256) {
        int kb = e >> 6, d = e & 63;
        float s = 0.f;
        const float* p = k + (kb * 64) * DD + d;
        for (int r = 0; r < 64; r++) s += p[r * DD];
        km[kb][d] = s * (1.f / 64.f);
    }
    if (tid < NQ) qsim[tid] = 1e30f;
    if (tid < NK) ksim[tid] = 1e30f;
    __syncthreads();

    if (tid < NQ) {
        float s = 0.f;
        for (int d = 0; d < DD; d++) s += qm[tid][d] * qm[tid][d];
        qmnorm[tid] = sqrtf(s);
    }
    if (tid < NK) {
        float s = 0.f;
        for (int d = 0; d < DD; d++) s += km[tid][d] * km[tid][d];
        kmnorm[tid] = sqrtf(s);
    }
    __syncthreads();

    for (int row = tid; row < LL; row += 256) {
        int qb = row >> 7;
        const float* p = q + row * DD;
        float dot = 0.f, nn = 0.f;
        for (int d = 0; d < DD; d++) { float v = p[d]; dot += v * qm[qb][d]; nn += v * v; }
        float cosv = dot / ((sqrtf(nn) + 1e-6f) * (qmnorm[qb] + 1e-6f));
        atomicMinFloat(&qsim[qb], cosv);
    }
    for (int row = tid; row < LL; row += 256) {
        int kb = row >> 6;
        const float* p = k + row * DD;
        float dot = 0.f, nn = 0.f;
        for (int d = 0; d < DD; d++) { float v = p[d]; dot += v * km[kb][d]; nn += v * v; }
        float cosv = dot / ((sqrtf(nn) + 1e-6f) * (kmnorm[kb] + 1e-6f));
        atomicMinFloat(&ksim[kb], cosv);
    }
    __syncthreads();

    for (int e = tid; e < NQ * NK; e += 256) {
        int qi = e >> 5, ki = e & 31;
        float dot = 0.f;
        for (int d = 0; d < DD; d++) dot += qm[qi][d] * km[ki][d];
        pooled[qi][ki] = dot * SCALE;
    }
    __syncthreads();

    if (tid < NQ) {
        float vals[NK]; int idx[NK];
        float mx = -CUDART_INF_F;
        for (int i = 0; i < NK; i++) mx = fmaxf(mx, pooled[tid][i]);
        float sum = 0.f;
        for (int i = 0; i < NK; i++) { vals[i] = expf(pooled[tid][i] - mx); sum += vals[i]; }
        float inv = 1.f / sum;
        for (int i = 0; i < NK; i++) { vals[i] *= inv; idx[i] = i; }
        for (int i = 1; i < NK; i++) {
            float kv = vals[i]; int ki = idx[i];
            int j = i - 1;
            while (j >= 0 && vals[j] < kv) { vals[j+1] = vals[j]; idx[j+1] = idx[j]; j--; }
            vals[j+1] = kv; idx[j+1] = ki;
        }
        unsigned keep = 0u;
        float csum = 0.f;
        for (int i = 0; i < NK; i++) {
            if (csum < CDFTH) keep |= (1u << idx[i]);
            csum += vals[i];
        }
        bool qself = qsim[tid] > SIMTH;
        int* mrow = g_mask + (bh * NQ + tid) * NK;
        for (int ki = 0; ki < NK; ki++) {
            bool kself = ksim[ki] > SIMTH;
            mrow[ki] = (((keep >> ki) & 1u) || !qself || !kself) ? 1 : 0;
        }
    }
}

// ---------------------------------------------------------------------------
// Kernel 3: block-sparse flash attention, tf32 mma.sync (m16n8k8)
// grid = (32 q-tiles of 64 rows, 16 bh), 128 threads = 4 warps x 16 rows
// ---------------------------------------------------------------------------
#define AT_S 68
#define ATT_SMEM_FLOATS (3*64*AT_S + 4*16*AT_S)
#define ATT_SMEM_BYTES  (ATT_SMEM_FLOATS * 4)

extern __shared__ float sm_attn[];

__global__ void __launch_bounds__(128) attn_tf32() {
    const int qb = blockIdx.x;          // 64-row q tile (0..31)
    const int bh = blockIdx.y;          // 0..15
    const int b = bh >> 3, h = bh & 7;
    const int tid  = threadIdx.x;
    const int wid  = tid >> 5;
    const int lane = tid & 31;
    const int lr = lane >> 2;
    const int lc = lane & 3;

    float* Qs = sm_attn;                      // [64][68]
    float* Ks = Qs + 64 * AT_S;               // [64][68]
    float* Vs = Ks + 64 * AT_S;               // [64][68]
    float* Ps = Vs + 64 * AT_S + wid * 16 * AT_S;  // per-warp [16][68]

    const float* qg = g_q + ((size_t)bh * LL + qb * 64) * DD;
    for (int i = tid; i < 1024; i += 128) {
        int r = i >> 4, dg = i & 15;
        float4 v = *(const float4*)&qg[r * DD + dg * 4];
        float4 w;
        w.x = __uint_as_float(f2tf32(v.x * SCALE));
        w.y = __uint_as_float(f2tf32(v.y * SCALE));
        w.z = __uint_as_float(f2tf32(v.z * SCALE));
        w.w = __uint_as_float(f2tf32(v.w * SCALE));
        *(float4*)&Qs[r * AT_S + dg * 4] = w;
    }

    float o[8][4];
    #pragma unroll
    for (int nt = 0; nt < 8; nt++)
        #pragma unroll
        for (int j = 0; j < 4; j++) o[nt][j] = 0.f;
    float m0r = -CUDART_INF_F, m1r = -CUDART_INF_F;
    float l0 = 0.f, l1 = 0.f;

    const int* mrow = g_mask + (bh * NQ + (qb >> 1)) * NK;
    const float* kg = g_k + (size_t)bh * LL * DD;
    const float* vg = g_v + (size_t)bh * LL * DD;
    const float* Qw = Qs + (wid * 16) * AT_S;

    for (int kb = 0; kb < NK; kb++) {
        if (!mrow[kb]) continue;
        __syncthreads();

        const float* kp = kg + (size_t)(kb * 64) * DD;
        const float* vp = vg + (size_t)(kb * 64) * DD;
        for (int i = tid; i < 1024; i += 128) {
            int r = i >> 4, dg = i & 15;
            float4 kv = *(const float4*)&kp[r * DD + dg * 4];
            float4 vv = *(const float4*)&vp[r * DD + dg * 4];
            float4 kw, vw;
            kw.x = __uint_as_float(f2tf32(kv.x)); kw.y = __uint_as_float(f2tf32(kv.y));
            kw.z = __uint_as_float(f2tf32(kv.z)); kw.w = __uint_as_float(f2tf32(kv.w));
            vw.x = __uint_as_float(f2tf32(vv.x)); vw.y = __uint_as_float(f2tf32(vv.y));
            vw.z = __uint_as_float(f2tf32(vv.z)); vw.w = __uint_as_float(f2tf32(vv.w));
            *(float4*)&Ks[r * AT_S + dg * 4] = kw;
            *(float4*)&Vs[r * AT_S + dg * 4] = vw;
        }
        __syncthreads();

        float sc[8][4];
        #pragma unroll
        for (int nt = 0; nt < 8; nt++)
            #pragma unroll
            for (int j = 0; j < 4; j++) sc[nt][j] = 0.f;

        #pragma unroll
        for (int kk = 0; kk < 8; kk++) {
            int k0 = kk * 8;
            unsigned a0 = __float_as_uint(Qw[(lr    ) * AT_S + k0 + lc    ]);
            unsigned a1 = __float_as_uint(Qw[(lr + 8) * AT_S + k0 + lc    ]);
            unsigned a2 = __float_as_uint(Qw[(lr    ) * AT_S + k0 + lc + 4]);
            unsigned a3 = __float_as_uint(Qw[(lr + 8) * AT_S + k0 + lc + 4]);
            #pragma unroll
            for (int nt = 0; nt < 8; nt++) {
                unsigned b0 = __float_as_uint(Ks[(nt * 8 + lr) * AT_S + k0 + lc    ]);
                unsigned b1 = __float_as_uint(Ks[(nt * 8 + lr) * AT_S + k0 + lc + 4]);
                mma_tf32(sc[nt], a0, a1, a2, a3, b0, b1);
            }
        }

        float rl = -CUDART_INF_F, rh = -CUDART_INF_F;
        #pragma unroll
        for (int nt = 0; nt < 8; nt++) {
            rl = fmaxf(rl, fmaxf(sc[nt][0], sc[nt][1]));
            rh = fmaxf(rh, fmaxf(sc[nt][2], sc[nt][3]));
        }
        rl = fmaxf(rl, __shfl_xor_sync(0xffffffffu, rl, 1));
        rl = fmaxf(rl, __shfl_xor_sync(0xffffffffu, rl, 2));
        rh = fmaxf(rh, __shfl_xor_sync(0xffffffffu, rh, 1));
        rh = fmaxf(rh, __shfl_xor_sync(0xffffffffu, rh, 2));
        float mn0 = fmaxf(m0r, rl), mn1 = fmaxf(m1r, rh);
        float c0 = __expf(m0r - mn0), c1 = __expf(m1r - mn1);
        float s0 = 0.f, s1 = 0.f;
        #pragma unroll
        for (int nt = 0; nt < 8; nt++) {
            float p0 = __expf(sc[nt][0] - mn0);
            float p1 = __expf(sc[nt][1] - mn0);
            float p2 = __expf(sc[nt][2] - mn1);
            float p3 = __expf(sc[nt][3] - mn1);
            s0 += p0 + p1; s1 += p2 + p3;
            o[nt][0] *= c0; o[nt][1] *= c0;
            o[nt][2] *= c1; o[nt][3] *= c1;
            uint2 wlo = make_uint2(f2tf32(p0), f2tf32(p1));
            uint2 whi = make_uint2(f2tf32(p2), f2tf32(p3));
            *(uint2*)&Ps[(lr    ) * AT_S + nt * 8 + 2 * lc] = wlo;
            *(uint2*)&Ps[(lr + 8) * AT_S + nt * 8 + 2 * lc] = whi;
        }
        s0 += __shfl_xor_sync(0xffffffffu, s0, 1);
        s0 += __shfl_xor_sync(0xffffffffu, s0, 2);
        s1 += __shfl_xor_sync(0xffffffffu, s1, 1);
        s1 += __shfl_xor_sync(0xffffffffu, s1, 2);
        l0 = l0 * c0 + s0;
        l1 = l1 * c1 + s1;
        m0r = mn0; m1r = mn1;
        __syncwarp();

        #pragma unroll
        for (int kk = 0; kk < 8; kk++) {
            int k0 = kk * 8;
            unsigned a0 = __float_as_uint(Ps[(lr    ) * AT_S + k0 + lc    ]);
            unsigned a1 = __float_as_uint(Ps[(lr + 8) * AT_S + k0 + lc    ]);
            unsigned a2 = __float_as_uint(Ps[(lr    ) * AT_S + k0 + lc + 4]);
            unsigned a3 = __float_as_uint(Ps[(lr + 8) * AT_S + k0 + lc + 4]);
            #pragma unroll
            for (int nt = 0; nt < 8; nt++) {
                unsigned b0 = __float_as_uint(Vs[(k0 + lc    ) * AT_S + nt * 8 + lr]);
                unsigned b1 = __float_as_uint(Vs[(k0 + lc + 4) * AT_S + nt * 8 + lr]);
                mma_tf32(o[nt], a0, a1, a2, a3, b0, b1);
            }
        }
    }

    float inv0 = 1.f / l0, inv1 = 1.f / l1;
    int r0 = qb * 64 + wid * 16 + lr;
    float* og = g_o + (size_t)b * LL * CC + h * DD;
    #pragma unroll
    for (int nt = 0; nt < 8; nt++) {
        float2 w0 = make_float2(o[nt][0] * inv0, o[nt][1] * inv0);
        float2 w1 = make_float2(o[nt][2] * inv1, o[nt][3] * inv1);
        *(float2*)&og[(size_t)(r0    ) * CC + nt * 8 + 2 * lc] = w0;
        *(float2*)&og[(size_t)(r0 + 8) * CC + nt * 8 + 2 * lc] = w1;
    }
}

// ---------------------------------------------------------------------------
extern "C" void kernel_launch(void* const* d_in, const int* in_sizes, int n_in,
                              void* d_out, int out_size) {
    const float* x     = (const float*)d_in[0];
    const float* Wqkv  = (const float*)d_in[1];
    const float* bqkv  = (const float*)d_in[2];
    const float* Wproj = (const float*)d_in[3];
    const float* bproj = (const float*)d_in[4];
    float* out = (float*)d_out;

    cudaFuncSetAttribute(attn_tf32, cudaFuncAttributeMaxDynamicSharedMemorySize,
                         ATT_SMEM_BYTES);

    gemm_tf32<NQKV, true><<<dim3(NQKV / 64, MM / 128), 256>>>(x, Wqkv, bqkv, nullptr);
    meta_mask_kernel<<<BB * HH, 256>>>();
    attn_tf32<<<dim3(32, BB * HH), 128, ATT_SMEM_BYTES>>>();
    gemm_tf32<CC, false><<<dim3(CC / 64, MM / 128), 256>>>(nullptr, Wproj, bproj, out);
}

// round 8
// speedup vs baseline: 4.6042x; 1.5314x over previous
#include <cuda_runtime.h>
#include <cuda_bf16.h>
#include <math_constants.h>

// Problem constants
#define BB   2
#define LL   2048
#define CC   512
#define HH   8
#define DD   64
#define MM   (BB*LL)          // 4096 rows
#define NQKV (3*CC)           // 1536
#define NQ   16               // L/128 (mask Q-block granularity)
#define NK   32               // L/64
#define SCALE 0.125f          // D^-0.5
#define SIMTH 0.6f
#define CDFTH 0.98f

// Scratch (allocation-free rule -> device globals)
__device__ float g_q[BB*HH*LL*DD];     // [B,H,L,D]
__device__ float g_k[BB*HH*LL*DD];
__device__ float g_v[BB*HH*LL*DD];
__device__ float g_o[BB*LL*CC];        // [B,L,C]
__device__ int   g_mask[BB*HH*NQ*NK];  // 1 = keep block
__device__ float g_qm[BB*HH][NQ][DD];
__device__ float g_km[BB*HH][NK][DD];
__device__ float g_qsim[BB*HH][NQ];
__device__ float g_ksim[BB*HH][NK];

__device__ __forceinline__ unsigned f2tf32(float x) {
    unsigned r;
    asm("cvt.rna.tf32.f32 %0, %1;" : "=r"(r) : "f"(x));
    return r;
}

__device__ __forceinline__ void mma_tf32(float c[4],
                                         unsigned a0, unsigned a1, unsigned a2, unsigned a3,
                                         unsigned b0, unsigned b1) {
    asm volatile(
        "mma.sync.aligned.m16n8k8.row.col.f32.tf32.tf32.f32 "
        "{%0,%1,%2,%3}, {%4,%5,%6,%7}, {%8,%9}, {%0,%1,%2,%3};"
        : "+f"(c[0]), "+f"(c[1]), "+f"(c[2]), "+f"(c[3])
        : "r"(a0), "r"(a1), "r"(a2), "r"(a3), "r"(b0), "r"(b1));
}

__device__ __forceinline__ void cp16(unsigned smem_dst, const void* gsrc) {
    asm volatile("cp.async.ca.shared.global [%0], [%1], 16;"
                 :: "r"(smem_dst), "l"(gsrc));
}

__device__ __forceinline__ void atomicMinFloat(float* addr, float val) {
    int* ia = (int*)addr;
    int old = *ia;
    while (__int_as_float(old) > val) {
        int assumed = old;
        old = atomicCAS(ia, assumed, __float_as_int(val));
        if (old == assumed) break;
    }
}

// ---------------------------------------------------------------------------
// tf32 tensor-core GEMM: C[M,N] = A[M,K=512] @ B[K,N] + bias
// 128x64 tile, 256 threads = 8 warps (4M x 2N), cp.async double-buffered.
// A staged [128][36] raw fp32, B staged [32][72] raw fp32; tf32 cvt at
// operand load (conflict-free: 36%32=4 with 4lr+lc; 72%32=8 with 8lc+lr).
// ---------------------------------------------------------------------------
#define GA_ST 36
#define GB_ST 72
#define GA_FL (128*GA_ST)          // 4608
#define GB_FL (32*GB_ST)           // 2304
#define GEMM_SMEM_FLOATS (2*GA_FL + 2*GB_FL)
#define GEMM_SMEM_BYTES  (GEMM_SMEM_FLOATS*4)

extern __shared__ float sm_dyn[];

template<int N, bool SCATTER>
__global__ void __launch_bounds__(256) gemm_tf32(const float* __restrict__ A,
                                                 const float* __restrict__ Bw,
                                                 const float* __restrict__ bias,
                                                 float* __restrict__ out) {
    const int K = CC;
    const float* Ap = SCATTER ? A : (const float*)g_o;
    int m0 = blockIdx.y * 128, n0 = blockIdx.x * 64;
    float* Asm = sm_dyn;                 // [2][GA_FL]
    float* Bsm = sm_dyn + 2 * GA_FL;     // [2][GB_FL]
    unsigned sbase = (unsigned)__cvta_generic_to_shared(sm_dyn);
    int tid = threadIdx.x;
    int wid = tid >> 5, lane = tid & 31;
    int lr = lane >> 2, lc = lane & 3;
    int warp_m = wid & 3, warp_n = wid >> 2;

    float c[2][4][4] = {};

    auto stage = [&](int buf, int k0) {
        unsigned a_s = sbase + (unsigned)(buf * GA_FL) * 4u;
        unsigned b_s = sbase + (unsigned)(2 * GA_FL + buf * GB_FL) * 4u;
        #pragma unroll
        for (int i = 0; i < 4; i++) {
            int f4 = tid + i * 256;              // 1024 f4 of A (128x32)
            int r = f4 >> 3, cg = f4 & 7;
            cp16(a_s + (unsigned)(r * GA_ST + cg * 4) * 4u,
                 &Ap[(size_t)(m0 + r) * K + k0 + cg * 4]);
        }
        #pragma unroll
        for (int i = 0; i < 2; i++) {
            int f4 = tid + i * 256;              // 512 f4 of B (32x64)
            int r = f4 >> 4, ng = f4 & 15;
            cp16(b_s + (unsigned)(r * GB_ST + ng * 4) * 4u,
                 &Bw[(size_t)(k0 + r) * N + n0 + ng * 4]);
        }
        asm volatile("cp.async.commit_group;");
    };

    stage(0, 0);
    const int NCHUNK = K / 32;   // 16
    for (int ch = 0; ch < NCHUNK; ch++) {
        int buf = ch & 1;
        if (ch < NCHUNK - 1) {
            stage(buf ^ 1, (ch + 1) * 32);
            asm volatile("cp.async.wait_group 1;");
        } else {
            asm volatile("cp.async.wait_group 0;");
        }
        __syncthreads();

        const float* Aw = Asm + buf * GA_FL + (warp_m * 32) * GA_ST;
        const float* Bb = Bsm + buf * GB_FL;
        #pragma unroll
        for (int kk = 0; kk < 4; kk++) {
            int kf = kk * 8;
            unsigned a[2][4];
            #pragma unroll
            for (int mt = 0; mt < 2; mt++) {
                a[mt][0] = f2tf32(Aw[(mt * 16 + lr    ) * GA_ST + kf + lc    ]);
                a[mt][1] = f2tf32(Aw[(mt * 16 + lr + 8) * GA_ST + kf + lc    ]);
                a[mt][2] = f2tf32(Aw[(mt * 16 + lr    ) * GA_ST + kf + lc + 4]);
                a[mt][3] = f2tf32(Aw[(mt * 16 + lr + 8) * GA_ST + kf + lc + 4]);
            }
            unsigned bf[4][2];
            #pragma unroll
            for (int nt = 0; nt < 4; nt++) {
                int nn = warp_n * 32 + nt * 8 + lr;
                bf[nt][0] = f2tf32(Bb[(kf + lc    ) * GB_ST + nn]);
                bf[nt][1] = f2tf32(Bb[(kf + lc + 4) * GB_ST + nn]);
            }
            #pragma unroll
            for (int mt = 0; mt < 2; mt++)
                #pragma unroll
                for (int nt = 0; nt < 4; nt++)
                    mma_tf32(c[mt][nt], a[mt][0], a[mt][1], a[mt][2], a[mt][3],
                             bf[nt][0], bf[nt][1]);
        }
        __syncthreads();
    }

    // Epilogue (fp32 bias add)
    #pragma unroll
    for (int mt = 0; mt < 2; mt++) {
        #pragma unroll
        for (int half = 0; half < 2; half++) {
            int row = m0 + warp_m * 32 + mt * 16 + lr + half * 8;
            #pragma unroll
            for (int nt = 0; nt < 4; nt++) {
                int col = n0 + warp_n * 32 + nt * 8 + 2 * lc;
                float v0 = c[mt][nt][half * 2 + 0] + bias[col];
                float v1 = c[mt][nt][half * 2 + 1] + bias[col + 1];
                if (SCATTER) {
                    int b = row >> 11, l = row & 2047;
                    int t = col >> 9;
                    int h = (col & 511) >> 6;
                    int d = col & 63;
                    float* dst = (t == 0) ? g_q : (t == 1) ? g_k : g_v;
                    *(float2*)&dst[((size_t)(b * HH + h) * LL + l) * DD + d] =
                        make_float2(v0, v1);
                } else {
                    *(float2*)&out[(size_t)row * N + col] = make_float2(v0, v1);
                }
            }
        }
    }
}

// ---------------------------------------------------------------------------
// Kernel 2a: per-block mean + min-cosine.  grid = (48, 16bh): x<16 -> Q block,
// else K block.  256 threads, coalesced loads, warp reductions.
// ---------------------------------------------------------------------------
__global__ void __launch_bounds__(256) meansim_kernel() {
    int bh = blockIdx.y;
    int j  = blockIdx.x;
    bool isQ = j < NQ;
    int blk  = isQ ? j : j - NQ;
    int rows = isQ ? 128 : 64;
    const float* base = (isQ ? g_q : g_k) + (size_t)bh * LL * DD + (size_t)blk * rows * DD;
    __shared__ float psum[256];
    __shared__ float mean[64];
    __shared__ float nrm;
    __shared__ float simv;
    int tid = threadIdx.x;
    if (tid == 0) simv = 1e30f;

    {   // column partial sums, 4 row-groups
        int d = tid & 63, rg = tid >> 6;
        float acc = 0.f;
        for (int r = rg; r < rows; r += 4) acc += base[r * DD + d];
        psum[tid] = acc;
    }
    __syncthreads();
    if (tid < 64) {
        float m = (psum[tid] + psum[tid + 64] + psum[tid + 128] + psum[tid + 192])
                  * (1.f / rows);
        mean[tid] = m;
        float* gm = isQ ? &g_qm[bh][blk][0] : &g_km[bh][blk][0];
        gm[tid] = m;
    }
    __syncthreads();
    if (tid < 32) {
        float s = mean[tid] * mean[tid] + mean[tid + 32] * mean[tid + 32];
        #pragma unroll
        for (int o = 16; o >= 1; o >>= 1) s += __shfl_xor_sync(0xffffffffu, s, o);
        if (tid == 0) nrm = sqrtf(s);
    }
    __syncthreads();
    float mnorm = nrm;

    float cosv;
    if (isQ) {        // 2 threads per row, 32 dims each
        int row = tid >> 1, half = tid & 1;
        const float* p  = base + row * DD + half * 32;
        const float* mp = mean + half * 32;
        float dot = 0.f, nn = 0.f;
        #pragma unroll
        for (int d = 0; d < 32; d++) { float v = p[d]; dot += v * mp[d]; nn += v * v; }
        dot += __shfl_xor_sync(0xffffffffu, dot, 1);
        nn  += __shfl_xor_sync(0xffffffffu, nn,  1);
        cosv = dot / ((sqrtf(nn) + 1e-6f) * (mnorm + 1e-6f));
    } else {          // 4 threads per row, 16 dims each
        int row = tid >> 2, qd = tid & 3;
        const float* p  = base + row * DD + qd * 16;
        const float* mp = mean + qd * 16;
        float dot = 0.f, nn = 0.f;
        #pragma unroll
        for (int d = 0; d < 16; d++) { float v = p[d]; dot += v * mp[d]; nn += v * v; }
        dot += __shfl_xor_sync(0xffffffffu, dot, 1);
        dot += __shfl_xor_sync(0xffffffffu, dot, 2);
        nn  += __shfl_xor_sync(0xffffffffu, nn,  1);
        nn  += __shfl_xor_sync(0xffffffffu, nn,  2);
        cosv = dot / ((sqrtf(nn) + 1e-6f) * (mnorm + 1e-6f));
    }
    #pragma unroll
    for (int o = 16; o >= 1; o >>= 1)
        cosv = fminf(cosv, __shfl_xor_sync(0xffffffffu, cosv, o));
    if ((tid & 31) == 0) atomicMinFloat(&simv, cosv);
    __syncthreads();
    if (tid == 0) {
        if (isQ) g_qsim[bh][blk] = simv; else g_ksim[bh][blk] = simv;
    }
}

// ---------------------------------------------------------------------------
// Kernel 2b: pooled softmax + CDF keep -> block mask.  grid = 16 bh.
// ---------------------------------------------------------------------------
__global__ void __launch_bounds__(256) mask_kernel() {
    int bh = blockIdx.x;
    __shared__ float pooled[NQ][NK];
    __shared__ float qs[NQ], kss[NK];
    int tid = threadIdx.x;
    if (tid < NQ) qs[tid]  = g_qsim[bh][tid];
    if (tid < NK) kss[tid] = g_ksim[bh][tid];
    for (int e = tid; e < NQ * NK; e += 256) {
        int qi = e >> 5, ki = e & 31;
        const float* a = g_qm[bh][qi];
        const float* b = g_km[bh][ki];
        float dot = 0.f;
        #pragma unroll
        for (int d = 0; d < DD; d++) dot += a[d] * b[d];
        pooled[qi][ki] = dot * SCALE;
    }
    __syncthreads();
    if (tid < NQ) {
        float vals[NK]; int idx[NK];
        float mx = -CUDART_INF_F;
        for (int i = 0; i < NK; i++) mx = fmaxf(mx, pooled[tid][i]);
        float sum = 0.f;
        for (int i = 0; i < NK; i++) { vals[i] = expf(pooled[tid][i] - mx); sum += vals[i]; }
        float inv = 1.f / sum;
        for (int i = 0; i < NK; i++) { vals[i] *= inv; idx[i] = i; }
        for (int i = 1; i < NK; i++) {
            float kv = vals[i]; int ki = idx[i];
            int j = i - 1;
            while (j >= 0 && vals[j] < kv) { vals[j+1] = vals[j]; idx[j+1] = idx[j]; j--; }
            vals[j+1] = kv; idx[j+1] = ki;
        }
        unsigned keep = 0u;
        float csum = 0.f;
        for (int i = 0; i < NK; i++) {
            if (csum < CDFTH) keep |= (1u << idx[i]);
            csum += vals[i];
        }
        bool qself = qs[tid] > SIMTH;
        int* mrow = g_mask + (bh * NQ + tid) * NK;
        for (int ki = 0; ki < NK; ki++) {
            bool kself = kss[ki] > SIMTH;
            mrow[ki] = (((keep >> ki) & 1u) || !qself || !kself) ? 1 : 0;
        }
    }
}

// ---------------------------------------------------------------------------
// Kernel 3: block-sparse flash attention, tf32 mma.sync
// grid = (16 q-tiles of 128 rows, 16 bh), 256 threads = 8 warps x 16 rows.
// K/V staged raw fp32 via cp.async (stride 68); tf32 cvt at operand load.
// ---------------------------------------------------------------------------
#define AT_S 68
#define AT_Q_FL (128*AT_S)                 // 8704
#define AT_K_FL (64*AT_S)                  // 4352
#define ATT_SMEM_FLOATS (AT_Q_FL + 2*AT_K_FL + 8*16*AT_S)
#define ATT_SMEM_BYTES  (ATT_SMEM_FLOATS*4)   // 104448

__global__ void __launch_bounds__(256, 2) attn_tf32() {
    const int qb = blockIdx.x;          // 128-row q tile (0..15) == mask block
    const int bh = blockIdx.y;
    const int b = bh >> 3, h = bh & 7;
    const int tid  = threadIdx.x;
    const int wid  = tid >> 5;
    const int lane = tid & 31;
    const int lr = lane >> 2;
    const int lc = lane & 3;

    float* Qs = sm_dyn;                                  // [128][68] tf32*scale
    float* Ks = Qs + AT_Q_FL;                            // [64][68] raw fp32
    float* Vs = Ks + AT_K_FL;                            // [64][68] raw fp32
    float* Ps = Vs + AT_K_FL + wid * 16 * AT_S;          // per-warp [16][68]
    unsigned sbase = (unsigned)__cvta_generic_to_shared(sm_dyn);
    unsigned ks_u = sbase + AT_Q_FL * 4u;
    unsigned vs_u = ks_u + AT_K_FL * 4u;

    // Stage Q (pre-scaled, tf32-rounded)
    const float* qg = g_q + ((size_t)bh * LL + qb * 128) * DD;
    for (int i = tid; i < 2048; i += 256) {
        int r = i >> 4, dg = i & 15;
        float4 v = *(const float4*)&qg[r * DD + dg * 4];
        float4 w;
        w.x = __uint_as_float(f2tf32(v.x * SCALE));
        w.y = __uint_as_float(f2tf32(v.y * SCALE));
        w.z = __uint_as_float(f2tf32(v.z * SCALE));
        w.w = __uint_as_float(f2tf32(v.w * SCALE));
        *(float4*)&Qs[r * AT_S + dg * 4] = w;
    }

    float o[8][4];
    #pragma unroll
    for (int nt = 0; nt < 8; nt++)
        #pragma unroll
        for (int j = 0; j < 4; j++) o[nt][j] = 0.f;
    float m0r = -CUDART_INF_F, m1r = -CUDART_INF_F;
    float l0 = 0.f, l1 = 0.f;

    const int* mrow = g_mask + (bh * NQ + qb) * NK;
    const float* kg = g_k + (size_t)bh * LL * DD;
    const float* vg = g_v + (size_t)bh * LL * DD;
    const float* Qw = Qs + (wid * 16) * AT_S;

    for (int kb = 0; kb < NK; kb++) {
        if (!mrow[kb]) continue;
        __syncthreads();               // prev iter's K/V reads done (+Q staged)

        // cp.async stage K,V raw fp32
        const float* kp = kg + (size_t)(kb * 64) * DD;
        const float* vp = vg + (size_t)(kb * 64) * DD;
        #pragma unroll
        for (int i = 0; i < 4; i++) {
            int f4 = tid + i * 256;    // 0..1023
            int r = f4 >> 4, cg = f4 & 15;
            unsigned off = (unsigned)(r * AT_S + cg * 4) * 4u;
            cp16(ks_u + off, kp + r * DD + cg * 4);
            cp16(vs_u + off, vp + r * DD + cg * 4);
        }
        asm volatile("cp.async.commit_group;");
        asm volatile("cp.async.wait_group 0;");
        __syncthreads();

        // S = Q K^T : warp computes 16 q rows x 64 kpos
        float sc[8][4];
        #pragma unroll
        for (int nt = 0; nt < 8; nt++)
            #pragma unroll
            for (int j = 0; j < 4; j++) sc[nt][j] = 0.f;

        #pragma unroll
        for (int kk = 0; kk < 8; kk++) {
            int k0 = kk * 8;
            unsigned a0 = __float_as_uint(Qw[(lr    ) * AT_S + k0 + lc    ]);
            unsigned a1 = __float_as_uint(Qw[(lr + 8) * AT_S + k0 + lc    ]);
            unsigned a2 = __float_as_uint(Qw[(lr    ) * AT_S + k0 + lc + 4]);
            unsigned a3 = __float_as_uint(Qw[(lr + 8) * AT_S + k0 + lc + 4]);
            #pragma unroll
            for (int nt = 0; nt < 8; nt++) {
                unsigned b0 = f2tf32(Ks[(nt * 8 + lr) * AT_S + k0 + lc    ]);
                unsigned b1 = f2tf32(Ks[(nt * 8 + lr) * AT_S + k0 + lc + 4]);
                mma_tf32(sc[nt], a0, a1, a2, a3, b0, b1);
            }
        }

        // Online softmax update (rows lr and lr+8 of the warp's 16)
        float rl = -CUDART_INF_F, rh = -CUDART_INF_F;
        #pragma unroll
        for (int nt = 0; nt < 8; nt++) {
            rl = fmaxf(rl, fmaxf(sc[nt][0], sc[nt][1]));
            rh = fmaxf(rh, fmaxf(sc[nt][2], sc[nt][3]));
        }
        rl = fmaxf(rl, __shfl_xor_sync(0xffffffffu, rl, 1));
        rl = fmaxf(rl, __shfl_xor_sync(0xffffffffu, rl, 2));
        rh = fmaxf(rh, __shfl_xor_sync(0xffffffffu, rh, 1));
        rh = fmaxf(rh, __shfl_xor_sync(0xffffffffu, rh, 2));
        float mn0 = fmaxf(m0r, rl), mn1 = fmaxf(m1r, rh);
        float c0 = __expf(m0r - mn0), c1 = __expf(m1r - mn1);
        float s0 = 0.f, s1 = 0.f;
        #pragma unroll
        for (int nt = 0; nt < 8; nt++) {
            float p0 = __expf(sc[nt][0] - mn0);
            float p1 = __expf(sc[nt][1] - mn0);
            float p2 = __expf(sc[nt][2] - mn1);
            float p3 = __expf(sc[nt][3] - mn1);
            s0 += p0 + p1; s1 += p2 + p3;
            o[nt][0] *= c0; o[nt][1] *= c0;
            o[nt][2] *= c1; o[nt][3] *= c1;
            uint2 wlo = make_uint2(f2tf32(p0), f2tf32(p1));
            uint2 whi = make_uint2(f2tf32(p2), f2tf32(p3));
            *(uint2*)&Ps[(lr    ) * AT_S + nt * 8 + 2 * lc] = wlo;
            *(uint2*)&Ps[(lr + 8) * AT_S + nt * 8 + 2 * lc] = whi;
        }
        s0 += __shfl_xor_sync(0xffffffffu, s0, 1);
        s0 += __shfl_xor_sync(0xffffffffu, s0, 2);
        s1 += __shfl_xor_sync(0xffffffffu, s1, 1);
        s1 += __shfl_xor_sync(0xffffffffu, s1, 2);
        l0 = l0 * c0 + s0;
        l1 = l1 * c1 + s1;
        m0r = mn0; m1r = mn1;
        __syncwarp();

        // O += P @ V (P warp-private; V cvt at load)
        #pragma unroll
        for (int kk = 0; kk < 8; kk++) {
            int k0 = kk * 8;
            unsigned a0 = __float_as_uint(Ps[(lr    ) * AT_S + k0 + lc    ]);
            unsigned a1 = __float_as_uint(Ps[(lr + 8) * AT_S + k0 + lc    ]);
            unsigned a2 = __float_as_uint(Ps[(lr    ) * AT_S + k0 + lc + 4]);
            unsigned a3 = __float_as_uint(Ps[(lr + 8) * AT_S + k0 + lc + 4]);
            #pragma unroll
            for (int nt = 0; nt < 8; nt++) {
                unsigned b0 = f2tf32(Vs[(k0 + lc    ) * AT_S + nt * 8 + lr]);
                unsigned b1 = f2tf32(Vs[(k0 + lc + 4) * AT_S + nt * 8 + lr]);
                mma_tf32(o[nt], a0, a1, a2, a3, b0, b1);
            }
        }
    }

    // Epilogue: normalize and scatter to g_o
    float inv0 = 1.f / l0, inv1 = 1.f / l1;
    int r0 = qb * 128 + wid * 16 + lr;
    float* og = g_o + (size_t)b * LL * CC + h * DD;
    #pragma unroll
    for (int nt = 0; nt < 8; nt++) {
        float2 w0 = make_float2(o[nt][0] * inv0, o[nt][1] * inv0);
        float2 w1 = make_float2(o[nt][2] * inv1, o[nt][3] * inv1);
        *(float2*)&og[(size_t)(r0    ) * CC + nt * 8 + 2 * lc] = w0;
        *(float2*)&og[(size_t)(r0 + 8) * CC + nt * 8 + 2 * lc] = w1;
    }
}

// ---------------------------------------------------------------------------
extern "C" void kernel_launch(void* const* d_in, const int* in_sizes, int n_in,
                              void* d_out, int out_size) {
    const float* x     = (const float*)d_in[0];
    const float* Wqkv  = (const float*)d_in[1];
    const float* bqkv  = (const float*)d_in[2];
    const float* Wproj = (const float*)d_in[3];
    const float* bproj = (const float*)d_in[4];
    float* out = (float*)d_out;

    cudaFuncSetAttribute(attn_tf32, cudaFuncAttributeMaxDynamicSharedMemorySize,
                         ATT_SMEM_BYTES);
    cudaFuncSetAttribute(gemm_tf32<NQKV, true>,
                         cudaFuncAttributeMaxDynamicSharedMemorySize, GEMM_SMEM_BYTES);
    cudaFuncSetAttribute(gemm_tf32<CC, false>,
                         cudaFuncAttributeMaxDynamicSharedMemorySize, GEMM_SMEM_BYTES);

    gemm_tf32<NQKV, true><<<dim3(NQKV / 64, MM / 128), 256, GEMM_SMEM_BYTES>>>(
        x, Wqkv, bqkv, nullptr);
    meansim_kernel<<<dim3(NQ + NK, BB * HH), 256>>>();
    mask_kernel<<<BB * HH, 256>>>();
    attn_tf32<<<dim3(NQ, BB * HH), 256, ATT_SMEM_BYTES>>>();
    gemm_tf32<CC, false><<<dim3(CC / 64, MM / 128), 256, GEMM_SMEM_BYTES>>>(
        nullptr, Wproj, bproj, out);
}

// round 10
// speedup vs baseline: 5.2800x; 1.1468x over previous
#include <cuda_runtime.h>
#include <cuda_bf16.h>
#include <math_constants.h>

// Problem constants
#define BB   2
#define LL   2048
#define CC   512
#define HH   8
#define DD   64
#define MM   (BB*LL)          // 4096 rows
#define NQKV (3*CC)           // 1536
#define NQ   16               // L/128 (mask Q-block granularity)
#define NK   32               // L/64
#define SCALE 0.125f          // D^-0.5
#define SIMTH 0.6f
#define CDFTH 0.98f

// Scratch (allocation-free rule -> device globals)
__device__ float g_q[BB*HH*LL*DD];        // raw [B,H,L,D] (meansim)
__device__ float g_k[BB*HH*LL*DD];        // raw [B,H,L,D] (meansim)
__device__ float g_qp[BB*HH*NQ*8192];     // Q A-fragments, tf32(q*SCALE)  (128x64)
__device__ float g_kp[BB*HH*NK*4096];     // K B-frag pairs, tf32          (64x64)
__device__ float g_vp[BB*HH*NK*4096];     // V B-frag pairs, tf32          (64x64)
__device__ float g_o[BB*LL*CC];           // [B,L,C]
__device__ int   g_mask[BB*HH*NQ*NK];     // 1 = keep block
__device__ float g_qm[BB*HH][NQ][DD];
__device__ float g_km[BB*HH][NK][DD];
__device__ float g_qsim[BB*HH][NQ];
__device__ float g_ksim[BB*HH][NK];

__device__ __forceinline__ unsigned f2tf32(float x) {
    unsigned r;
    asm("cvt.rna.tf32.f32 %0, %1;" : "=r"(r) : "f"(x));
    return r;
}
__device__ __forceinline__ float tf32f(float x) {
    return __uint_as_float(f2tf32(x));
}

__device__ __forceinline__ void mma_tf32(float c[4],
                                         unsigned a0, unsigned a1, unsigned a2, unsigned a3,
                                         unsigned b0, unsigned b1) {
    asm volatile(
        "mma.sync.aligned.m16n8k8.row.col.f32.tf32.tf32.f32 "
        "{%0,%1,%2,%3}, {%4,%5,%6,%7}, {%8,%9}, {%0,%1,%2,%3};"
        : "+f"(c[0]), "+f"(c[1]), "+f"(c[2]), "+f"(c[3])
        : "r"(a0), "r"(a1), "r"(a2), "r"(a3), "r"(b0), "r"(b1));
}

__device__ __forceinline__ void cp16(unsigned smem_dst, const void* gsrc) {
    asm volatile("cp.async.ca.shared.global [%0], [%1], 16;"
                 :: "r"(smem_dst), "l"(gsrc));
}

__device__ __forceinline__ void atomicMinFloat(float* addr, float val) {
    int* ia = (int*)addr;
    int old = *ia;
    while (__int_as_float(old) > val) {
        int assumed = old;
        old = atomicCAS(ia, assumed, __float_as_int(val));
        if (old == assumed) break;
    }
}

// ---------------------------------------------------------------------------
// tf32 tensor-core GEMM: C[M,N] = A[M,K=512] @ B[K,N] + bias
// 128x64 tile, 256 threads = 8 warps (4M x 2N), cp.async double-buffered.
// SCATTER=true: writes raw q/k + fragment-packed qp/kp/vp.
// ---------------------------------------------------------------------------
#define GA_ST 36
#define GB_ST 72
#define GA_FL (128*GA_ST)          // 4608
#define GB_FL (32*GB_ST)           // 2304
#define GEMM_SMEM_FLOATS (2*GA_FL + 2*GB_FL)
#define GEMM_SMEM_BYTES  (GEMM_SMEM_FLOATS*4)

extern __shared__ float sm_dyn[];

template<int N, bool SCATTER>
__global__ void __launch_bounds__(256) gemm_tf32(const float* __restrict__ A,
                                                 const float* __restrict__ Bw,
                                                 const float* __restrict__ bias,
                                                 float* __restrict__ out) {
    const int K = CC;
    const float* Ap = SCATTER ? A : (const float*)g_o;
    int m0 = blockIdx.y * 128, n0 = blockIdx.x * 64;
    float* Asm = sm_dyn;
    float* Bsm = sm_dyn + 2 * GA_FL;
    unsigned sbase = (unsigned)__cvta_generic_to_shared(sm_dyn);
    int tid = threadIdx.x;
    int wid = tid >> 5, lane = tid & 31;
    int lr = lane >> 2, lc = lane & 3;
    int warp_m = wid & 3, warp_n = wid >> 2;

    float c[2][4][4] = {};

    auto stage = [&](int buf, int k0) {
        unsigned a_s = sbase + (unsigned)(buf * GA_FL) * 4u;
        unsigned b_s = sbase + (unsigned)(2 * GA_FL + buf * GB_FL) * 4u;
        #pragma unroll
        for (int i = 0; i < 4; i++) {
            int f4 = tid + i * 256;
            int r = f4 >> 3, cg = f4 & 7;
            cp16(a_s + (unsigned)(r * GA_ST + cg * 4) * 4u,
                 &Ap[(size_t)(m0 + r) * K + k0 + cg * 4]);
        }
        #pragma unroll
        for (int i = 0; i < 2; i++) {
            int f4 = tid + i * 256;
            int r = f4 >> 4, ng = f4 & 15;
            cp16(b_s + (unsigned)(r * GB_ST + ng * 4) * 4u,
                 &Bw[(size_t)(k0 + r) * N + n0 + ng * 4]);
        }
        asm volatile("cp.async.commit_group;");
    };

    stage(0, 0);
    const int NCHUNK = K / 32;
    for (int ch = 0; ch < NCHUNK; ch++) {
        int buf = ch & 1;
        if (ch < NCHUNK - 1) {
            stage(buf ^ 1, (ch + 1) * 32);
            asm volatile("cp.async.wait_group 1;");
        } else {
            asm volatile("cp.async.wait_group 0;");
        }
        __syncthreads();

        const float* Aw = Asm + buf * GA_FL + (warp_m * 32) * GA_ST;
        const float* Bb = Bsm + buf * GB_FL;
        #pragma unroll
        for (int kk = 0; kk < 4; kk++) {
            int kf = kk * 8;
            unsigned a[2][4];
            #pragma unroll
            for (int mt = 0; mt < 2; mt++) {
                a[mt][0] = f2tf32(Aw[(mt * 16 + lr    ) * GA_ST + kf + lc    ]);
                a[mt][1] = f2tf32(Aw[(mt * 16 + lr + 8) * GA_ST + kf + lc    ]);
                a[mt][2] = f2tf32(Aw[(mt * 16 + lr    ) * GA_ST + kf + lc + 4]);
                a[mt][3] = f2tf32(Aw[(mt * 16 + lr + 8) * GA_ST + kf + lc + 4]);
            }
            unsigned bf[4][2];
            #pragma unroll
            for (int nt = 0; nt < 4; nt++) {
                int nn = warp_n * 32 + nt * 8 + lr;
                bf[nt][0] = f2tf32(Bb[(kf + lc    ) * GB_ST + nn]);
                bf[nt][1] = f2tf32(Bb[(kf + lc + 4) * GB_ST + nn]);
            }
            #pragma unroll
            for (int mt = 0; mt < 2; mt++)
                #pragma unroll
                for (int nt = 0; nt < 4; nt++)
                    mma_tf32(c[mt][nt], a[mt][0], a[mt][1], a[mt][2], a[mt][3],
                             bf[nt][0], bf[nt][1]);
        }
        __syncthreads();
    }

    // Epilogue
    int t = n0 >> 9;   // uniform per CTA when SCATTER
    #pragma unroll
    for (int mt = 0; mt < 2; mt++) {
        #pragma unroll
        for (int half = 0; half < 2; half++) {
            int row = m0 + warp_m * 32 + mt * 16 + lr + half * 8;
            #pragma unroll
            for (int nt = 0; nt < 4; nt++) {
                int col = n0 + warp_n * 32 + nt * 8 + 2 * lc;
                float v0 = c[mt][nt][half * 2 + 0] + bias[col];
                float v1 = c[mt][nt][half * 2 + 1] + bias[col + 1];
                if (SCATTER) {
                    int b = row >> 11, l = row & 2047;
                    int h = (col & 511) >> 6;
                    int d = col & 63, d1 = d + 1;
                    int bh = b * HH + h;
                    if (t == 0) {
                        *(float2*)&g_q[((size_t)bh * LL + l) * DD + d] =
                            make_float2(v0, v1);
                        int qt = l >> 7, r = l & 127;
                        int w = r >> 4, lr2 = r & 7, hf = (r >> 3) & 1;
                        float* qp = g_qp + ((size_t)(bh * NQ + qt)) * 8192 + w * 1024;
                        qp[(d  >> 3) * 128 + (lr2 * 4 + (d  & 3)) * 4 + hf + 2 * ((d  >> 2) & 1)]
                            = tf32f(v0 * SCALE);
                        qp[(d1 >> 3) * 128 + (lr2 * 4 + (d1 & 3)) * 4 + hf + 2 * ((d1 >> 2) & 1)]
                            = tf32f(v1 * SCALE);
                    } else if (t == 1) {
                        *(float2*)&g_k[((size_t)bh * LL + l) * DD + d] =
                            make_float2(v0, v1);
                        int kb = l >> 6, n = l & 63;
                        float* kp = g_kp + ((size_t)(bh * NK + kb)) * 4096 + n * 8;
                        kp[(d  >> 3) * 512 + (d  & 3) * 2 + ((d  >> 2) & 1)] = tf32f(v0);
                        kp[(d1 >> 3) * 512 + (d1 & 3) * 2 + ((d1 >> 2) & 1)] = tf32f(v1);
                    } else {
                        int kb = l >> 6, k64 = l & 63;
                        float* vp = g_vp + ((size_t)(bh * NK + kb)) * 4096
                                  + (k64 >> 3) * 512 + (k64 & 3) * 2 + ((k64 >> 2) & 1);
                        vp[d  * 8] = tf32f(v0);
                        vp[d1 * 8] = tf32f(v1);
                    }
                } else {
                    *(float2*)&out[(size_t)row * N + col] = make_float2(v0, v1);
                }
            }
        }
    }
}

// ---------------------------------------------------------------------------
// Kernel 2a: per-block mean + min-cosine.
// ---------------------------------------------------------------------------
__global__ void __launch_bounds__(256) meansim_kernel() {
    int bh = blockIdx.y;
    int j  = blockIdx.x;
    bool isQ = j < NQ;
    int blk  = isQ ? j : j - NQ;
    int rows = isQ ? 128 : 64;
    const float* base = (isQ ? g_q : g_k) + (size_t)bh * LL * DD + (size_t)blk * rows * DD;
    __shared__ float psum[256];
    __shared__ float mean[64];
    __shared__ float nrm;
    __shared__ float simv;
    int tid = threadIdx.x;
    if (tid == 0) simv = 1e30f;

    {
        int d = tid & 63, rg = tid >> 6;
        float acc = 0.f;
        for (int r = rg; r < rows; r += 4) acc += base[r * DD + d];
        psum[tid] = acc;
    }
    __syncthreads();
    if (tid < 64) {
        float m = (psum[tid] + psum[tid + 64] + psum[tid + 128] + psum[tid + 192])
                  * (1.f / rows);
        mean[tid] = m;
        float* gm = isQ ? &g_qm[bh][blk][0] : &g_km[bh][blk][0];
        gm[tid] = m;
    }
    __syncthreads();
    if (tid < 32) {
        float s = mean[tid] * mean[tid] + mean[tid + 32] * mean[tid + 32];
        #pragma unroll
        for (int o = 16; o >= 1; o >>= 1) s += __shfl_xor_sync(0xffffffffu, s, o);
        if (tid == 0) nrm = sqrtf(s);
    }
    __syncthreads();
    float mnorm = nrm;

    float cosv;
    if (isQ) {
        int row = tid >> 1, half = tid & 1;
        const float* p  = base + row * DD + half * 32;
        const float* mp = mean + half * 32;
        float dot = 0.f, nn = 0.f;
        #pragma unroll
        for (int d = 0; d < 32; d++) { float v = p[d]; dot += v * mp[d]; nn += v * v; }
        dot += __shfl_xor_sync(0xffffffffu, dot, 1);
        nn  += __shfl_xor_sync(0xffffffffu, nn,  1);
        cosv = dot / ((sqrtf(nn) + 1e-6f) * (mnorm + 1e-6f));
    } else {
        int row = tid >> 2, qd = tid & 3;
        const float* p  = base + row * DD + qd * 16;
        const float* mp = mean + qd * 16;
        float dot = 0.f, nn = 0.f;
        #pragma unroll
        for (int d = 0; d < 16; d++) { float v = p[d]; dot += v * mp[d]; nn += v * v; }
        dot += __shfl_xor_sync(0xffffffffu, dot, 1);
        dot += __shfl_xor_sync(0xffffffffu, dot, 2);
        nn  += __shfl_xor_sync(0xffffffffu, nn,  1);
        nn  += __shfl_xor_sync(0xffffffffu, nn,  2);
        cosv = dot / ((sqrtf(nn) + 1e-6f) * (mnorm + 1e-6f));
    }
    #pragma unroll
    for (int o = 16; o >= 1; o >>= 1)
        cosv = fminf(cosv, __shfl_xor_sync(0xffffffffu, cosv, o));
    if ((tid & 31) == 0) atomicMinFloat(&simv, cosv);
    __syncthreads();
    if (tid == 0) {
        if (isQ) g_qsim[bh][blk] = simv; else g_ksim[bh][blk] = simv;
    }
}

// ---------------------------------------------------------------------------
// Kernel 2b: pooled softmax + CDF keep -> block mask.
// ---------------------------------------------------------------------------
__global__ void __launch_bounds__(256) mask_kernel() {
    int bh = blockIdx.x;
    __shared__ float pooled[NQ][NK];
    __shared__ float qs[NQ], kss[NK];
    int tid = threadIdx.x;
    if (tid < NQ) qs[tid]  = g_qsim[bh][tid];
    if (tid < NK) kss[tid] = g_ksim[bh][tid];
    for (int e = tid; e < NQ * NK; e += 256) {
        int qi = e >> 5, ki = e & 31;
        const float* a = g_qm[bh][qi];
        const float* b = g_km[bh][ki];
        float dot = 0.f;
        #pragma unroll
        for (int d = 0; d < DD; d++) dot += a[d] * b[d];
        pooled[qi][ki] = dot * SCALE;
    }
    __syncthreads();
    if (tid < NQ) {
        float vals[NK]; int idx[NK];
        float mx = -CUDART_INF_F;
        for (int i = 0; i < NK; i++) mx = fmaxf(mx, pooled[tid][i]);
        float sum = 0.f;
        for (int i = 0; i < NK; i++) { vals[i] = expf(pooled[tid][i] - mx); sum += vals[i]; }
        float inv = 1.f / sum;
        for (int i = 0; i < NK; i++) { vals[i] *= inv; idx[i] = i; }
        for (int i = 1; i < NK; i++) {
            float kv = vals[i]; int ki = idx[i];
            int j = i - 1;
            while (j >= 0 && vals[j] < kv) { vals[j+1] = vals[j]; idx[j+1] = idx[j]; j--; }
            vals[j+1] = kv; idx[j+1] = ki;
        }
        unsigned keep = 0u;
        float csum = 0.f;
        for (int i = 0; i < NK; i++) {
            if (csum < CDFTH) keep |= (1u << idx[i]);
            csum += vals[i];
        }
        bool qself = qs[tid] > SIMTH;
        int* mrow = g_mask + (bh * NQ + tid) * NK;
        for (int ki = 0; ki < NK; ki++) {
            bool kself = kss[ki] > SIMTH;
            mrow[ki] = (((keep >> ki) & 1u) || !qself || !kself) ? 1 : 0;
        }
    }
}

// ---------------------------------------------------------------------------
// Kernel 3: block-sparse flash attention, tf32 mma, fragment-packed operands.
// grid = (16 q-tiles of 128 rows, 16 bh), 256 threads = 8 warps.
// smem: Qp[8192] | Kp[4096] | Vp[4096] | Pp[8 warps][1024]  = 96KB.
// All operand loads are LDS.128 / LDS.64, conflict-free.
// ---------------------------------------------------------------------------
#define ATT_SMEM_FLOATS (8192 + 4096 + 4096 + 8192)
#define ATT_SMEM_BYTES  (ATT_SMEM_FLOATS * 4)      // 98304

__global__ void __launch_bounds__(256, 2) attn_tf32() {
    const int qb = blockIdx.x;
    const int bh = blockIdx.y;
    const int b = bh >> 3, h = bh & 7;
    const int tid  = threadIdx.x;
    const int wid  = tid >> 5;
    const int lane = tid & 31;
    const int lr = lane >> 2;
    const int lc = lane & 3;

    float* Qp  = sm_dyn;                 // [8 w][8 kk][32 lane][4]
    float* Kp  = sm_dyn + 8192;          // [8 kk][64 n][8]  (frag pairs)
    float* Vp  = Kp + 4096;              // [8 kk][64 n][8]
    float* PpW = Vp + 4096 + wid * 1024; // [8 kk][2 c2][32 L][2]
    unsigned sbase = (unsigned)__cvta_generic_to_shared(sm_dyn);
    unsigned kp_u = sbase + 8192u * 4u;
    unsigned vp_u = kp_u + 4096u * 4u;

    // Stage Q fragments (precomputed, tf32*scale): 8192 floats
    const float* qsrc = g_qp + ((size_t)(bh * NQ + qb)) * 8192;
    #pragma unroll
    for (int i = 0; i < 8; i++)
        cp16(sbase + (unsigned)(tid + i * 256) * 16u, qsrc + (tid + i * 256) * 4);
    asm volatile("cp.async.commit_group;");

    float o[8][4];
    #pragma unroll
    for (int nt = 0; nt < 8; nt++)
        #pragma unroll
        for (int j = 0; j < 4; j++) o[nt][j] = 0.f;
    float m0r = -CUDART_INF_F, m1r = -CUDART_INF_F;
    float l0 = 0.f, l1 = 0.f;

    const int* mrow = g_mask + (bh * NQ + qb) * NK;
    const float* QpW = Qp + wid * 1024;

    for (int kb = 0; kb < NK; kb++) {
        if (!mrow[kb]) continue;
        __syncthreads();               // prev K/V reads complete

        const float* ks = g_kp + ((size_t)(bh * NK + kb)) * 4096;
        const float* vs = g_vp + ((size_t)(bh * NK + kb)) * 4096;
        #pragma unroll
        for (int i = 0; i < 4; i++) {  // 1024 float4 each
            cp16(kp_u + (unsigned)(tid + i * 256) * 16u, ks + (tid + i * 256) * 4);
            cp16(vp_u + (unsigned)(tid + i * 256) * 16u, vs + (tid + i * 256) * 4);
        }
        asm volatile("cp.async.commit_group;");
        asm volatile("cp.async.wait_group 0;");
        __syncthreads();

        // S = Q K^T
        float sc[8][4];
        #pragma unroll
        for (int nt = 0; nt < 8; nt++)
            #pragma unroll
            for (int j = 0; j < 4; j++) sc[nt][j] = 0.f;

        #pragma unroll
        for (int kk = 0; kk < 8; kk++) {
            float4 av = *(const float4*)(QpW + kk * 128 + lane * 4);
            unsigned a0 = __float_as_uint(av.x), a1 = __float_as_uint(av.y);
            unsigned a2 = __float_as_uint(av.z), a3 = __float_as_uint(av.w);
            const float* kbase = Kp + kk * 512 + lr * 8 + lc * 2;
            #pragma unroll
            for (int nt = 0; nt < 8; nt++) {
                float2 bv = *(const float2*)(kbase + nt * 64);
                mma_tf32(sc[nt], a0, a1, a2, a3,
                         __float_as_uint(bv.x), __float_as_uint(bv.y));
            }
        }

        // Online softmax (rows lr, lr+8)
        float rl = -CUDART_INF_F, rh = -CUDART_INF_F;
        #pragma unroll
        for (int nt = 0; nt < 8; nt++) {
            rl = fmaxf(rl, fmaxf(sc[nt][0], sc[nt][1]));
            rh = fmaxf(rh, fmaxf(sc[nt][2], sc[nt][3]));
        }
        rl = fmaxf(rl, __shfl_xor_sync(0xffffffffu, rl, 1));
        rl = fmaxf(rl, __shfl_xor_sync(0xffffffffu, rl, 2));
        rh = fmaxf(rh, __shfl_xor_sync(0xffffffffu, rh, 1));
        rh = fmaxf(rh, __shfl_xor_sync(0xffffffffu, rh, 2));
        float mn0 = fmaxf(m0r, rl), mn1 = fmaxf(m1r, rh);
        float c0 = __expf(m0r - mn0), c1 = __expf(m1r - mn1);
        float s0 = 0.f, s1 = 0.f;
        #pragma unroll
        for (int nt = 0; nt < 8; nt++) {
            float p0 = __expf(sc[nt][0] - mn0);
            float p1 = __expf(sc[nt][1] - mn0);
            float p2 = __expf(sc[nt][2] - mn1);
            float p3 = __expf(sc[nt][3] - mn1);
            s0 += p0 + p1; s1 += p2 + p3;
            o[nt][0] *= c0; o[nt][1] *= c0;
            o[nt][2] *= c1; o[nt][3] *= c1;
            // Pp[kk=nt][c2][L=lane][2]: c2=0 holds (p0,p2), c2=1 holds (p1,p3)
            *(float2*)(PpW + nt * 128 +      lane * 2) = make_float2(tf32f(p0), tf32f(p2));
            *(float2*)(PpW + nt * 128 + 64 + lane * 2) = make_float2(tf32f(p1), tf32f(p3));
        }
        s0 += __shfl_xor_sync(0xffffffffu, s0, 1);
        s0 += __shfl_xor_sync(0xffffffffu, s0, 2);
        s1 += __shfl_xor_sync(0xffffffffu, s1, 1);
        s1 += __shfl_xor_sync(0xffffffffu, s1, 2);
        l0 = l0 * c0 + s0;
        l1 = l1 * c1 + s1;
        m0r = mn0; m1r = mn1;
        __syncwarp();

        // O += P @ V
        #pragma unroll
        for (int kk = 0; kk < 8; kk++) {
            const float* pb = PpW + kk * 128 + (lc & 1) * 64 + (lr * 4 + (lc >> 1)) * 2;
            float2 A01 = *(const float2*)pb;        // a0 = P[lr][8kk+lc], a1 = P[lr+8][..]
            float2 A23 = *(const float2*)(pb + 4);  // a2, a3 (cols +4)
            unsigned a0 = __float_as_uint(A01.x), a1 = __float_as_uint(A01.y);
            unsigned a2 = __float_as_uint(A23.x), a3 = __float_as_uint(A23.y);
            const float* vbase = Vp + kk * 512 + lr * 8 + lc * 2;
            #pragma unroll
            for (int nt = 0; nt < 8; nt++) {
                float2 bv = *(const float2*)(vbase + nt * 64);
                mma_tf32(o[nt], a0, a1, a2, a3,
                         __float_as_uint(bv.x), __float_as_uint(bv.y));
            }
        }
    }

    // Epilogue: normalize and scatter to g_o
    float inv0 = 1.f / l0, inv1 = 1.f / l1;
    int r0 = qb * 128 + wid * 16 + lr;
    float* og = g_o + (size_t)b * LL * CC + h * DD;
    #pragma unroll
    for (int nt = 0; nt < 8; nt++) {
        float2 w0 = make_float2(o[nt][0] * inv0, o[nt][1] * inv0);
        float2 w1 = make_float2(o[nt][2] * inv1, o[nt][3] * inv1);
        *(float2*)&og[(size_t)(r0    ) * CC + nt * 8 + 2 * lc] = w0;
        *(float2*)&og[(size_t)(r0 + 8) * CC + nt * 8 + 2 * lc] = w1;
    }
}

// ---------------------------------------------------------------------------
extern "C" void kernel_launch(void* const* d_in, const int* in_sizes, int n_in,
                              void* d_out, int out_size) {
    const float* x     = (const float*)d_in[0];
    const float* Wqkv  = (const float*)d_in[1];
    const float* bqkv  = (const float*)d_in[2];
    const float* Wproj = (const float*)d_in[3];
    const float* bproj = (const float*)d_in[4];
    float* out = (float*)d_out;

    cudaFuncSetAttribute(attn_tf32, cudaFuncAttributeMaxDynamicSharedMemorySize,
                         ATT_SMEM_BYTES);
    cudaFuncSetAttribute(gemm_tf32<NQKV, true>,
                         cudaFuncAttributeMaxDynamicSharedMemorySize, GEMM_SMEM_BYTES);
    cudaFuncSetAttribute(gemm_tf32<CC, false>,
                         cudaFuncAttributeMaxDynamicSharedMemorySize, GEMM_SMEM_BYTES);

    gemm_tf32<NQKV, true><<<dim3(NQKV / 64, MM / 128), 256, GEMM_SMEM_BYTES>>>(
        x, Wqkv, bqkv, nullptr);
    meansim_kernel<<<dim3(NQ + NK, BB * HH), 256>>>();
    mask_kernel<<<BB * HH, 256>>>();
    attn_tf32<<<dim3(NQ, BB * HH), 256, ATT_SMEM_BYTES>>>();
    gemm_tf32<CC, false><<<dim3(CC / 64, MM / 128), 256, GEMM_SMEM_BYTES>>>(
        nullptr, Wproj, bproj, out);
}